// round 8
// baseline (speedup 1.0000x reference)
#include <cuda_runtime.h>
#include <math.h>

// Problem constants
#define BATCH  8
#define SEQ    1024
#define DMODEL 1024
#define HEADS  16
#define HDIM   64
#define MTOT   (BATCH * SEQ)          // 8192

// -------------------- scratch (__device__ globals; no allocs allowed) -------
__device__ float g_q[(size_t)BATCH * HEADS * SEQ * HDIM];   // [B,H,S,Hd] (tf32-rounded)
__device__ float g_k[(size_t)BATCH * HEADS * SEQ * HDIM];
__device__ float g_v[(size_t)BATCH * HEADS * SEQ * HDIM];
__device__ float g_ctx[(size_t)BATCH * SEQ * DMODEL];       // [B,S,D] (tf32-rounded)
__device__ float g_xr[(size_t)MTOT * DMODEL];               // rounded x
__device__ float g_wr[4][(size_t)DMODEL * DMODEL];          // rounded Wq,Wk,Wv,Wo

// -------------------- helpers ------------------------------------------------
__device__ __forceinline__ float rndf(float f) {   // round-to-nearest tf32, as fp32
    unsigned u;
    asm("cvt.rna.tf32.f32 %0, %1;" : "=r"(u) : "f"(f));
    return __uint_as_float(u);
}

__device__ __forceinline__ void cpa16(void* smem, const void* gmem) {
    unsigned sa = (unsigned)__cvta_generic_to_shared(smem);
    asm volatile("cp.async.cg.shared.global [%0], [%1], 16;\n" :: "r"(sa), "l"(gmem));
}
#define CP_COMMIT() asm volatile("cp.async.commit_group;\n")

// D = A(16x8,row)*B(8x8,col)+D, tf32 (operands pre-rounded -> truncation exact)
__device__ __forceinline__ void mma8(float* c, const unsigned* a, const unsigned* b) {
    asm volatile(
        "mma.sync.aligned.m16n8k8.row.col.f32.tf32.tf32.f32 "
        "{%0,%1,%2,%3}, {%4,%5,%6,%7}, {%8,%9}, {%0,%1,%2,%3};\n"
        : "+f"(c[0]), "+f"(c[1]), "+f"(c[2]), "+f"(c[3])
        : "r"(a[0]), "r"(a[1]), "r"(a[2]), "r"(a[3]), "r"(b[0]), "r"(b[1]));
}

// =============================================================================
// Elementwise tf32 rounding pre-pass (float4 vectorized)
// =============================================================================
__global__ __launch_bounds__(256)
void round_tf32_kernel(float* __restrict__ dst, const float* __restrict__ src, int n4)
{
    int i = blockIdx.x * blockDim.x + threadIdx.x;
    if (i < n4) {
        float4 v = ((const float4*)src)[i];
        v.x = rndf(v.x); v.y = rndf(v.y); v.z = rndf(v.z); v.w = rndf(v.w);
        ((float4*)dst)[i] = v;
    }
}

// =============================================================================
// Projection GEMM: C[M,1024] = A[M,1024] * W[1024,1024]^T + bias
// BM=128, BN=128, BK=32; 8 warps, warp tile 64x32. 3-stage cp.async pipeline.
// =============================================================================
#define PSTR 36
#define PBUF (128 * PSTR)
#define PNT  (DMODEL / 32)
#define PROJ_SMEM_BYTES (3 * 2 * PBUF * 4)   // 110592

__global__ __launch_bounds__(256, 2)
void proj_tf32_kernel(const float* __restrict__ A, const float* __restrict__ W,
                      const float* __restrict__ bias, float* __restrict__ C,
                      int split_heads)
{
    extern __shared__ float psm[];

    const int tid  = threadIdx.x;
    const int wid  = tid >> 5;
    const int lane = tid & 31;
    const int gid  = lane >> 2;
    const int tig  = lane & 3;
    const int m0 = blockIdx.y * 128;
    const int n0 = blockIdx.x * 128;
    const int wm = (wid >> 2) * 64;
    const int wn = (wid & 3) * 32;

    const int lrow = tid >> 3;
    const int lc4  = (tid & 7) * 4;

    float acc[4][4][4];
#pragma unroll
    for (int mt = 0; mt < 4; mt++)
#pragma unroll
        for (int nt = 0; nt < 4; nt++)
#pragma unroll
            for (int r = 0; r < 4; r++) acc[mt][nt][r] = 0.0f;

    auto load_tile = [&](int kt, int s) {
        float* As = psm + s * 2 * PBUF;
        float* Bs = As + PBUF;
#pragma unroll
        for (int r = 0; r < 4; r++) {
            int row = lrow + r * 32;
            cpa16(&As[row * PSTR + lc4], A + (size_t)(m0 + row) * DMODEL + kt + lc4);
            cpa16(&Bs[row * PSTR + lc4], W + (size_t)(n0 + row) * DMODEL + kt + lc4);
        }
    };

    load_tile(0, 0); CP_COMMIT();
    load_tile(32, 1); CP_COMMIT();

    for (int t = 0; t < PNT; t++) {
        if (t + 2 < PNT) { load_tile((t + 2) * 32, (t + 2) % 3); CP_COMMIT(); }
        if (t + 2 < PNT)      asm volatile("cp.async.wait_group 2;\n");
        else if (t + 1 < PNT) asm volatile("cp.async.wait_group 1;\n");
        else                  asm volatile("cp.async.wait_group 0;\n");
        __syncthreads();

        const unsigned* Ab = (const unsigned*)(psm + (t % 3) * 2 * PBUF);
        const unsigned* Bb = Ab + PBUF;
#pragma unroll
        for (int ks = 0; ks < 4; ks++) {
            unsigned af[4][4], bf[4][2];
#pragma unroll
            for (int mt = 0; mt < 4; mt++) {
                const unsigned* p  = &Ab[(wm + mt * 16 + gid) * PSTR + ks * 8 + tig];
                const unsigned* p2 = p + 8 * PSTR;
                af[mt][0] = p[0];  af[mt][2] = p[4];
                af[mt][1] = p2[0]; af[mt][3] = p2[4];
            }
#pragma unroll
            for (int nt = 0; nt < 4; nt++) {
                const unsigned* p = &Bb[(wn + nt * 8 + gid) * PSTR + ks * 8 + tig];
                bf[nt][0] = p[0]; bf[nt][1] = p[4];
            }
#pragma unroll
            for (int mt = 0; mt < 4; mt++)
#pragma unroll
                for (int nt = 0; nt < 4; nt++)
                    mma8(acc[mt][nt], af[mt], bf[nt]);
        }
        __syncthreads();
    }

#pragma unroll
    for (int mt = 0; mt < 4; mt++) {
#pragma unroll
        for (int half = 0; half < 2; half++) {
            int m  = m0 + wm + mt * 16 + gid + half * 8;
            int bb = m >> 10;
            int s  = m & 1023;
#pragma unroll
            for (int nt = 0; nt < 4; nt++) {
                int n = n0 + wn + nt * 8 + tig * 2;
                float2 v;
                v.x = acc[mt][nt][half * 2 + 0] + bias[n];
                v.y = acc[mt][nt][half * 2 + 1] + bias[n + 1];
                size_t idx;
                if (split_heads) {
                    v.x = rndf(v.x); v.y = rndf(v.y);   // consumed by tf32 GEMMs
                    int h = n >> 6, d = n & 63;
                    idx = ((((size_t)bb * HEADS + h) * SEQ + s) << 6) + d;
                } else {
                    idx = (size_t)m * DMODEL + n;
                }
                *(float2*)(C + idx) = v;
            }
        }
    }
}

// =============================================================================
// Fused two-pass attention. One block = (bh, 64 query rows), 256 thr, 8 warps.
// Pass 1: scores mma over 16 K-tiles, rowsum of rnd(exp(s/8)) in registers.
// Pass 2: recompute scores; write attn = e_r*inv; ctx = rnd((sum e_r*V)*inv).
// Warp layout: scores -> warp w owns keys [w*8, w*8+8) of each tile;
//              ctx    -> warp w owns d-cols [w*8, w*8+8), P tile via smem.
// =============================================================================
#define FQSTR 68
#define FKSTR 68
#define FVSTR 72
#define FPSTR 68
#define FQ_U (64 * FQSTR)
#define FK_U (64 * FKSTR)
#define FV_U (64 * FVSTR)
#define FP_U (64 * FPSTR)
#define FNT  (SEQ / 64)     // 16
#define FUSED_SMEM_BYTES ((FQ_U + 2 * FK_U + 2 * FV_U + FP_U) * 4)   // 106496

__global__ __launch_bounds__(256, 2)
void attn_fused2_kernel(const float* __restrict__ q, const float* __restrict__ k,
                        const float* __restrict__ v, float* __restrict__ attn,
                        float* __restrict__ ctx)
{
    extern __shared__ float fsm[];
    float* Qs = fsm;                    // [64][FQSTR]
    float* Ks = Qs + FQ_U;              // [2][64][FKSTR]
    float* Vs = Ks + 2 * FK_U;          // [2][64][FVSTR]
    float* Ps = Vs + 2 * FV_U;          // [64][FPSTR]
    __shared__ float ssum[64];
    __shared__ float sinv[64];

    const int tid  = threadIdx.x;
    const int wid  = tid >> 5;          // 0..7
    const int lane = tid & 31;
    const int gid  = lane >> 2;         // 0..7
    const int tig  = lane & 3;          // 0..3
    const int bh = blockIdx.y;
    const int q0 = blockIdx.x * 64;
    const int b = bh >> 4, h = bh & 15;

    const float* qb = q + ((size_t)bh * SEQ + q0) * HDIM;
    const float* kb = k + (size_t)bh * SEQ * HDIM;
    const float* vb = v + (size_t)bh * SEQ * HDIM;

    const int lrow = tid >> 4;          // 0..15 (+16*r)
    const int lc4  = (tid & 15) * 4;    // 0..60

    if (tid < 64) ssum[tid] = 0.0f;

    auto loadQ = [&]() {
#pragma unroll
        for (int r = 0; r < 4; r++) {
            int row = lrow + r * 16;
            cpa16(&Qs[row * FQSTR + lc4], qb + (size_t)row * HDIM + lc4);
        }
    };
    auto loadK = [&](int t, int s) {
        float* Kd = Ks + s * FK_U;
#pragma unroll
        for (int r = 0; r < 4; r++) {
            int row = lrow + r * 16;
            cpa16(&Kd[row * FKSTR + lc4], kb + (size_t)(t * 64 + row) * HDIM + lc4);
        }
    };
    auto loadV = [&](int t, int s) {
        float* Vd = Vs + s * FV_U;
#pragma unroll
        for (int r = 0; r < 4; r++) {
            int row = lrow + r * 16;
            cpa16(&Vd[row * FVSTR + lc4], vb + (size_t)(t * 64 + row) * HDIM + lc4);
        }
    };

    // ---------------- PASS 1: rowsums ----------------
    loadQ(); loadK(0, 0); CP_COMMIT();

    float rs[4][2];
#pragma unroll
    for (int mt = 0; mt < 4; mt++) { rs[mt][0] = 0.0f; rs[mt][1] = 0.0f; }

    for (int t = 0; t < FNT; t++) {
        if (t + 1 < FNT) { loadK(t + 1, (t + 1) & 1); CP_COMMIT(); }
        if (t + 1 < FNT) asm volatile("cp.async.wait_group 1;\n");
        else             asm volatile("cp.async.wait_group 0;\n");
        __syncthreads();

        const unsigned* Qu = (const unsigned*)Qs;
        const unsigned* Ku = (const unsigned*)(Ks + (t & 1) * FK_U);

        float acc[4][4];
#pragma unroll
        for (int mt = 0; mt < 4; mt++)
#pragma unroll
            for (int r = 0; r < 4; r++) acc[mt][r] = 0.0f;

#pragma unroll
        for (int ks = 0; ks < 8; ks++) {
            unsigned af[4][4], bf[2];
            const unsigned* pB = &Ku[(wid * 8 + gid) * FKSTR + ks * 8 + tig];
            bf[0] = pB[0]; bf[1] = pB[4];
#pragma unroll
            for (int mt = 0; mt < 4; mt++) {
                const unsigned* p  = &Qu[(mt * 16 + gid) * FQSTR + ks * 8 + tig];
                const unsigned* p2 = p + 8 * FQSTR;
                af[mt][0] = p[0];  af[mt][2] = p[4];
                af[mt][1] = p2[0]; af[mt][3] = p2[4];
            }
#pragma unroll
            for (int mt = 0; mt < 4; mt++)
                mma8(acc[mt], af[mt], bf);
        }

#pragma unroll
        for (int mt = 0; mt < 4; mt++) {
            rs[mt][0] += rndf(__expf(acc[mt][0] * 0.125f)) + rndf(__expf(acc[mt][1] * 0.125f));
            rs[mt][1] += rndf(__expf(acc[mt][2] * 0.125f)) + rndf(__expf(acc[mt][3] * 0.125f));
        }
        __syncthreads();
    }

    // reduce rowsums: quad shfl, then cross-warp smem atomics
#pragma unroll
    for (int mt = 0; mt < 4; mt++) {
#pragma unroll
        for (int hf = 0; hf < 2; hf++) {
            rs[mt][hf] += __shfl_xor_sync(0xffffffffu, rs[mt][hf], 1);
            rs[mt][hf] += __shfl_xor_sync(0xffffffffu, rs[mt][hf], 2);
        }
    }
    if (tig == 0) {
#pragma unroll
        for (int mt = 0; mt < 4; mt++) {
            atomicAdd(&ssum[mt * 16 + gid], rs[mt][0]);
            atomicAdd(&ssum[mt * 16 + 8 + gid], rs[mt][1]);
        }
    }
    __syncthreads();
    if (tid < 64) sinv[tid] = 1.0f / ssum[tid];
    __syncthreads();

    float invr[4][2];
#pragma unroll
    for (int mt = 0; mt < 4; mt++) {
        invr[mt][0] = sinv[mt * 16 + gid];
        invr[mt][1] = sinv[mt * 16 + 8 + gid];
    }

    // ---------------- PASS 2: attn write + ctx ----------------
    float cacc[4][4];
#pragma unroll
    for (int mt = 0; mt < 4; mt++)
#pragma unroll
        for (int r = 0; r < 4; r++) cacc[mt][r] = 0.0f;

    loadK(0, 0); loadV(0, 0); CP_COMMIT();

    float* ab = attn + (size_t)bh * SEQ * SEQ;

    for (int t = 0; t < FNT; t++) {
        if (t + 1 < FNT) { loadK(t + 1, (t + 1) & 1); loadV(t + 1, (t + 1) & 1); CP_COMMIT(); }
        if (t + 1 < FNT) asm volatile("cp.async.wait_group 1;\n");
        else             asm volatile("cp.async.wait_group 0;\n");
        __syncthreads();

        const unsigned* Qu = (const unsigned*)Qs;
        const unsigned* Ku = (const unsigned*)(Ks + (t & 1) * FK_U);

        float acc[4][4];
#pragma unroll
        for (int mt = 0; mt < 4; mt++)
#pragma unroll
            for (int r = 0; r < 4; r++) acc[mt][r] = 0.0f;

#pragma unroll
        for (int ks = 0; ks < 8; ks++) {
            unsigned af[4][4], bf[2];
            const unsigned* pB = &Ku[(wid * 8 + gid) * FKSTR + ks * 8 + tig];
            bf[0] = pB[0]; bf[1] = pB[4];
#pragma unroll
            for (int mt = 0; mt < 4; mt++) {
                const unsigned* p  = &Qu[(mt * 16 + gid) * FQSTR + ks * 8 + tig];
                const unsigned* p2 = p + 8 * FQSTR;
                af[mt][0] = p[0];  af[mt][2] = p[4];
                af[mt][1] = p2[0]; af[mt][3] = p2[4];
            }
#pragma unroll
            for (int mt = 0; mt < 4; mt++)
                mma8(acc[mt], af[mt], bf);
        }

        // e_r -> attn (normalized) + P smem (unnormalized, tf32-exact)
        int colg = t * 64 + wid * 8 + tig * 2;
#pragma unroll
        for (int mt = 0; mt < 4; mt++) {
#pragma unroll
            for (int hf = 0; hf < 2; hf++) {
                int row_l = mt * 16 + gid + hf * 8;
                float e0 = rndf(__expf(acc[mt][hf * 2 + 0] * 0.125f));
                float e1 = rndf(__expf(acc[mt][hf * 2 + 1] * 0.125f));
                float2 pout;
                pout.x = e0 * invr[mt][hf];
                pout.y = e1 * invr[mt][hf];
                *(float2*)(ab + (size_t)(q0 + row_l) * SEQ + colg) = pout;
                float2 es; es.x = e0; es.y = e1;
                *(float2*)&Ps[row_l * FPSTR + wid * 8 + tig * 2] = es;
            }
        }
        __syncthreads();   // P tile complete

        // ctx mma: A = P (all keys of tile), B = V (warp's d-slice)
        const unsigned* Pu = (const unsigned*)Ps;
        const unsigned* Vu = (const unsigned*)(Vs + (t & 1) * FV_U);
#pragma unroll
        for (int ks = 0; ks < 8; ks++) {
            unsigned af[4][4], bf[2];
            const unsigned* pB = &Vu[(ks * 8 + tig) * FVSTR + wid * 8 + gid];
            bf[0] = pB[0]; bf[1] = pB[4 * FVSTR];
#pragma unroll
            for (int mt = 0; mt < 4; mt++) {
                const unsigned* p  = &Pu[(mt * 16 + gid) * FPSTR + ks * 8 + tig];
                const unsigned* p2 = p + 8 * FPSTR;
                af[mt][0] = p[0];  af[mt][2] = p[4];
                af[mt][1] = p2[0]; af[mt][3] = p2[4];
            }
#pragma unroll
            for (int mt = 0; mt < 4; mt++)
                mma8(cacc[mt], af[mt], bf);
        }
        __syncthreads();   // protect P + K/V buffers
    }

    // ctx epilogue: normalize rows, round, store [B,S,D]
#pragma unroll
    for (int mt = 0; mt < 4; mt++) {
#pragma unroll
        for (int hf = 0; hf < 2; hf++) {
            int row_l = mt * 16 + gid + hf * 8;
            int qrow = q0 + row_l;
            float* crow = ctx + ((size_t)b * SEQ + qrow) * DMODEL + h * HDIM + wid * 8 + tig * 2;
            float2 o;
            o.x = rndf(cacc[mt][hf * 2 + 0] * invr[mt][hf]);
            o.y = rndf(cacc[mt][hf * 2 + 1] * invr[mt][hf]);
            *(float2*)crow = o;
        }
    }
}

// -------------------- launcher ----------------------------------------------
extern "C" void kernel_launch(void* const* d_in, const int* in_sizes, int n_in,
                              void* d_out, int out_size)
{
    const float* x  = (const float*)d_in[0];
    const float* Wq = (const float*)d_in[1];
    const float* bq = (const float*)d_in[2];
    const float* Wk = (const float*)d_in[3];
    const float* bk = (const float*)d_in[4];
    const float* Wv = (const float*)d_in[5];
    const float* bv = (const float*)d_in[6];
    const float* Wo = (const float*)d_in[7];
    const float* bo = (const float*)d_in[8];

    float* out_ptr  = (float*)d_out;                                   // [B,S,D]
    float* attn_ptr = (float*)d_out + (size_t)BATCH * SEQ * DMODEL;    // [B,H,S,S]

    float *qp, *kp, *vp, *cp, *xr, *wr;
    cudaGetSymbolAddress((void**)&qp, g_q);
    cudaGetSymbolAddress((void**)&kp, g_k);
    cudaGetSymbolAddress((void**)&vp, g_v);
    cudaGetSymbolAddress((void**)&cp, g_ctx);
    cudaGetSymbolAddress((void**)&xr, g_xr);
    cudaGetSymbolAddress((void**)&wr, g_wr);

    cudaFuncSetAttribute(proj_tf32_kernel,
                         cudaFuncAttributeMaxDynamicSharedMemorySize, PROJ_SMEM_BYTES);
    cudaFuncSetAttribute(attn_fused2_kernel,
                         cudaFuncAttributeMaxDynamicSharedMemorySize, FUSED_SMEM_BYTES);

    dim3 blk(256);

    // pre-round inputs to tf32-representable fp32
    const size_t WSZ = (size_t)DMODEL * DMODEL;
    int xn4 = (int)((size_t)MTOT * DMODEL / 4);
    int wn4 = (int)(WSZ / 4);
    round_tf32_kernel<<<(xn4 + 255) / 256, blk>>>(xr, x, xn4);
    round_tf32_kernel<<<(wn4 + 255) / 256, blk>>>(wr + 0 * WSZ, Wq, wn4);
    round_tf32_kernel<<<(wn4 + 255) / 256, blk>>>(wr + 1 * WSZ, Wk, wn4);
    round_tf32_kernel<<<(wn4 + 255) / 256, blk>>>(wr + 2 * WSZ, Wv, wn4);
    round_tf32_kernel<<<(wn4 + 255) / 256, blk>>>(wr + 3 * WSZ, Wo, wn4);

    dim3 pgrid(DMODEL / 128, MTOT / 128);       // (8, 64)
    proj_tf32_kernel<<<pgrid, blk, PROJ_SMEM_BYTES>>>(xr, wr + 0 * WSZ, bq, qp, 1);
    proj_tf32_kernel<<<pgrid, blk, PROJ_SMEM_BYTES>>>(xr, wr + 1 * WSZ, bk, kp, 1);
    proj_tf32_kernel<<<pgrid, blk, PROJ_SMEM_BYTES>>>(xr, wr + 2 * WSZ, bv, vp, 1);

    dim3 fgrid(SEQ / 64, BATCH * HEADS);        // (16, 128)
    attn_fused2_kernel<<<fgrid, blk, FUSED_SMEM_BYTES>>>(qp, kp, vp, attn_ptr, cp);

    proj_tf32_kernel<<<pgrid, blk, PROJ_SMEM_BYTES>>>(cp, wr + 3 * WSZ, bo, out_ptr, 0);
}

// round 9
// speedup vs baseline: 1.2618x; 1.2618x over previous
#include <cuda_runtime.h>
#include <cuda_fp16.h>
#include <math.h>

// Problem constants
#define BATCH  8
#define SEQ    1024
#define DMODEL 1024
#define HEADS  16
#define HDIM   64
#define MTOT   (BATCH * SEQ)          // 8192

// -------------------- scratch (__device__ globals; no allocs allowed) -------
__device__ float g_q[(size_t)BATCH * HEADS * SEQ * HDIM];   // [B,H,S,Hd] (tf32-rounded)
__device__ float g_k[(size_t)BATCH * HEADS * SEQ * HDIM];
__device__ float g_v[(size_t)BATCH * HEADS * SEQ * HDIM];
__device__ float g_ctx[(size_t)BATCH * SEQ * DMODEL];       // [B,S,D] (tf32-rounded)
__device__ float g_rowsum[(size_t)BATCH * HEADS * SEQ * 8]; // [row][kb] partial exp sums
__device__ float g_xr[(size_t)MTOT * DMODEL];               // rounded x
__device__ float g_wr[4][(size_t)DMODEL * DMODEL];          // rounded Wq,Wk,Wv,Wo
__device__ __half g_eh[(size_t)BATCH * HEADS * SEQ * SEQ];  // unnormalized e (fp16)

// -------------------- helpers ------------------------------------------------
__device__ __forceinline__ float rndf(float f) {   // round-to-nearest tf32, as fp32
    unsigned u;
    asm("cvt.rna.tf32.f32 %0, %1;" : "=r"(u) : "f"(f));
    return __uint_as_float(u);
}

__device__ __forceinline__ __half2 ex2h2(float t0, float t1) {  // {2^t0, 2^t1}
    __half2 h = __floats2half2_rn(t0, t1);
    unsigned u = *(unsigned*)&h;
    asm("ex2.approx.f16x2 %0, %0;" : "+r"(u));
    return *(__half2*)&u;
}

__device__ __forceinline__ void cpa16(void* smem, const void* gmem) {
    unsigned sa = (unsigned)__cvta_generic_to_shared(smem);
    asm volatile("cp.async.cg.shared.global [%0], [%1], 16;\n" :: "r"(sa), "l"(gmem));
}
#define CP_COMMIT() asm volatile("cp.async.commit_group;\n")

// D = A(16x8,row)*B(8x8,col)+D, tf32 (operands pre-rounded -> truncation exact)
__device__ __forceinline__ void mma8(float* c, const unsigned* a, const unsigned* b) {
    asm volatile(
        "mma.sync.aligned.m16n8k8.row.col.f32.tf32.tf32.f32 "
        "{%0,%1,%2,%3}, {%4,%5,%6,%7}, {%8,%9}, {%0,%1,%2,%3};\n"
        : "+f"(c[0]), "+f"(c[1]), "+f"(c[2]), "+f"(c[3])
        : "r"(a[0]), "r"(a[1]), "r"(a[2]), "r"(a[3]), "r"(b[0]), "r"(b[1]));
}

// =============================================================================
// Elementwise tf32 rounding pre-pass (float4 vectorized)
// =============================================================================
__global__ __launch_bounds__(256)
void round_tf32_kernel(float* __restrict__ dst, const float* __restrict__ src, int n4)
{
    int i = blockIdx.x * blockDim.x + threadIdx.x;
    if (i < n4) {
        float4 v = ((const float4*)src)[i];
        v.x = rndf(v.x); v.y = rndf(v.y); v.z = rndf(v.z); v.w = rndf(v.w);
        ((float4*)dst)[i] = v;
    }
}

// =============================================================================
// Projection GEMM: C[M,1024] = A[M,1024] * W[1024,1024]^T + bias
// BM=128, BN=128, BK=32; 8 warps, warp tile 64x32. 3-stage cp.async pipeline.
// =============================================================================
#define PSTR 36
#define PBUF (128 * PSTR)
#define PNT  (DMODEL / 32)
#define PROJ_SMEM_BYTES (3 * 2 * PBUF * 4)   // 110592

__global__ __launch_bounds__(256, 2)
void proj_tf32_kernel(const float* __restrict__ A, const float* __restrict__ W,
                      const float* __restrict__ bias, float* __restrict__ C,
                      int split_heads)
{
    extern __shared__ float psm[];

    const int tid  = threadIdx.x;
    const int wid  = tid >> 5;
    const int lane = tid & 31;
    const int gid  = lane >> 2;
    const int tig  = lane & 3;
    const int m0 = blockIdx.y * 128;
    const int n0 = blockIdx.x * 128;
    const int wm = (wid >> 2) * 64;
    const int wn = (wid & 3) * 32;

    const int lrow = tid >> 3;
    const int lc4  = (tid & 7) * 4;

    float acc[4][4][4];
#pragma unroll
    for (int mt = 0; mt < 4; mt++)
#pragma unroll
        for (int nt = 0; nt < 4; nt++)
#pragma unroll
            for (int r = 0; r < 4; r++) acc[mt][nt][r] = 0.0f;

    auto load_tile = [&](int kt, int s) {
        float* As = psm + s * 2 * PBUF;
        float* Bs = As + PBUF;
#pragma unroll
        for (int r = 0; r < 4; r++) {
            int row = lrow + r * 32;
            cpa16(&As[row * PSTR + lc4], A + (size_t)(m0 + row) * DMODEL + kt + lc4);
            cpa16(&Bs[row * PSTR + lc4], W + (size_t)(n0 + row) * DMODEL + kt + lc4);
        }
    };

    load_tile(0, 0); CP_COMMIT();
    load_tile(32, 1); CP_COMMIT();

    for (int t = 0; t < PNT; t++) {
        if (t + 2 < PNT) { load_tile((t + 2) * 32, (t + 2) % 3); CP_COMMIT(); }
        if (t + 2 < PNT)      asm volatile("cp.async.wait_group 2;\n");
        else if (t + 1 < PNT) asm volatile("cp.async.wait_group 1;\n");
        else                  asm volatile("cp.async.wait_group 0;\n");
        __syncthreads();

        const unsigned* Ab = (const unsigned*)(psm + (t % 3) * 2 * PBUF);
        const unsigned* Bb = Ab + PBUF;
#pragma unroll
        for (int ks = 0; ks < 4; ks++) {
            unsigned af[4][4], bf[4][2];
#pragma unroll
            for (int mt = 0; mt < 4; mt++) {
                const unsigned* p  = &Ab[(wm + mt * 16 + gid) * PSTR + ks * 8 + tig];
                const unsigned* p2 = p + 8 * PSTR;
                af[mt][0] = p[0];  af[mt][2] = p[4];
                af[mt][1] = p2[0]; af[mt][3] = p2[4];
            }
#pragma unroll
            for (int nt = 0; nt < 4; nt++) {
                const unsigned* p = &Bb[(wn + nt * 8 + gid) * PSTR + ks * 8 + tig];
                bf[nt][0] = p[0]; bf[nt][1] = p[4];
            }
#pragma unroll
            for (int mt = 0; mt < 4; mt++)
#pragma unroll
                for (int nt = 0; nt < 4; nt++)
                    mma8(acc[mt][nt], af[mt], bf[nt]);
        }
        __syncthreads();
    }

#pragma unroll
    for (int mt = 0; mt < 4; mt++) {
#pragma unroll
        for (int half = 0; half < 2; half++) {
            int m  = m0 + wm + mt * 16 + gid + half * 8;
            int bb = m >> 10;
            int s  = m & 1023;
#pragma unroll
            for (int nt = 0; nt < 4; nt++) {
                int n = n0 + wn + nt * 8 + tig * 2;
                float2 v;
                v.x = acc[mt][nt][half * 2 + 0] + bias[n];
                v.y = acc[mt][nt][half * 2 + 1] + bias[n + 1];
                size_t idx;
                if (split_heads) {
                    v.x = rndf(v.x); v.y = rndf(v.y);   // consumed by tf32 GEMMs
                    int h = n >> 6, d = n & 63;
                    idx = ((((size_t)bb * HEADS + h) * SEQ + s) << 6) + d;
                } else {
                    idx = (size_t)m * DMODEL + n;
                }
                *(float2*)(C + idx) = v;
            }
        }
    }
}

// =============================================================================
// Scores: e = fp16(2^(s*0.125*log2e)) UNNORMALIZED into g_eh, per-block row
// partial sums into g_rowsum[row][kb]. Tiles 128x128, K=64, per (b,h).
// =============================================================================
#define SSTR 68
#define SCORES_SMEM_BYTES (2 * 128 * SSTR * 4)   // 69632
#define SCALE_LOG2E 0.18033688f   // 0.125 * log2(e)

__global__ __launch_bounds__(256, 2)
void scores_tf32_kernel(const float* __restrict__ q, const float* __restrict__ k,
                        __half* __restrict__ eh, float* __restrict__ rowsum)
{
    extern __shared__ float ssm[];
    float* Qs = ssm;                 // [128][SSTR]
    float* Ks = ssm + 128 * SSTR;    // [128][SSTR]
    __shared__ float sexp[128];

    const int tid  = threadIdx.x;
    const int wid  = tid >> 5;
    const int lane = tid & 31;
    const int gid  = lane >> 2;
    const int tig  = lane & 3;
    const int bh = blockIdx.z;
    const int q0 = blockIdx.y * 128;
    const int k0 = blockIdx.x * 128;
    const int kb = blockIdx.x;
    const int wm = (wid >> 2) * 64;
    const int wn = (wid & 3) * 32;

    const float* qb = q + (size_t)bh * SEQ * HDIM;
    const float* kp = k + (size_t)bh * SEQ * HDIM;

#pragma unroll
    for (int r = 0; r < 8; r++) {
        int idx = tid + r * 256;
        int row = idx >> 4;
        int c4  = (idx & 15) * 4;
        cpa16(&Qs[row * SSTR + c4], qb + (size_t)(q0 + row) * HDIM + c4);
        cpa16(&Ks[row * SSTR + c4], kp + (size_t)(k0 + row) * HDIM + c4);
    }
    CP_COMMIT();
    if (tid < 128) sexp[tid] = 0.0f;
    asm volatile("cp.async.wait_group 0;\n");
    __syncthreads();

    float acc[4][4][4];
#pragma unroll
    for (int mt = 0; mt < 4; mt++)
#pragma unroll
        for (int nt = 0; nt < 4; nt++)
#pragma unroll
            for (int r = 0; r < 4; r++) acc[mt][nt][r] = 0.0f;

    const unsigned* Qu = (const unsigned*)Qs;
    const unsigned* Ku = (const unsigned*)Ks;
#pragma unroll
    for (int ks = 0; ks < 8; ks++) {
        unsigned af[4][4], bf[4][2];
#pragma unroll
        for (int mt = 0; mt < 4; mt++) {
            const unsigned* p  = &Qu[(wm + mt * 16 + gid) * SSTR + ks * 8 + tig];
            const unsigned* p2 = p + 8 * SSTR;
            af[mt][0] = p[0];  af[mt][2] = p[4];
            af[mt][1] = p2[0]; af[mt][3] = p2[4];
        }
#pragma unroll
        for (int nt = 0; nt < 4; nt++) {
            const unsigned* p = &Ku[(wn + nt * 8 + gid) * SSTR + ks * 8 + tig];
            bf[nt][0] = p[0]; bf[nt][1] = p[4];
        }
#pragma unroll
        for (int mt = 0; mt < 4; mt++)
#pragma unroll
            for (int nt = 0; nt < 4; nt++)
                mma8(acc[mt][nt], af[mt], bf[nt]);
    }

    __half* eb = eh + (size_t)bh * SEQ * SEQ;
#pragma unroll
    for (int mt = 0; mt < 4; mt++) {
#pragma unroll
        for (int half = 0; half < 2; half++) {
            int lr = wm + mt * 16 + gid + half * 8;
            int sq = q0 + lr;
            float lsum = 0.0f;
#pragma unroll
            for (int nt = 0; nt < 4; nt++) {
                int sk = k0 + wn + nt * 8 + tig * 2;
                __half2 e2 = ex2h2(acc[mt][nt][half * 2 + 0] * SCALE_LOG2E,
                                   acc[mt][nt][half * 2 + 1] * SCALE_LOG2E);
                *(__half2*)(eb + (size_t)sq * SEQ + sk) = e2;
                float2 ef = __half22float2(e2);
                lsum += ef.x + ef.y;
            }
            lsum += __shfl_xor_sync(0xffffffffu, lsum, 1);
            lsum += __shfl_xor_sync(0xffffffffu, lsum, 2);
            if (tig == 0) atomicAdd(&sexp[lr], lsum);
        }
    }
    __syncthreads();
    if (tid < 128)
        rowsum[((size_t)bh * SEQ + q0 + tid) * 8 + kb] = sexp[tid];
}

// =============================================================================
// Context GEMM: read e (fp16), convert per tile -> fp32 P smem; write final
// attn = e*inv; ctx = rnd((sum e*V)*inv). BM=256, N=64, BK=32; 8 warps.
// =============================================================================
#define CSTR 36
#define VSTR 72
#define CV_U (32 * VSTR)         // V stage (floats)
#define CP2_U (256 * CSTR)       // fp32 P tile (floats)
#define PH_U (256 * 32)          // half staging stage (halfs), unpadded 64B rows
#define CTX_SMEM_BYTES ((2 * CV_U + CP2_U) * 4 + 2 * PH_U * 2)   // 88064

__global__ __launch_bounds__(256, 2)
void ctx_tf32_kernel(const __half* __restrict__ eh, const float* __restrict__ v,
                     const float* __restrict__ rowsum, float* __restrict__ attn,
                     float* __restrict__ ctx)
{
    extern __shared__ float csm[];
    float*  Vs  = csm;                        // [2][CV_U]
    float*  PS2 = csm + 2 * CV_U;             // [256][CSTR]
    __half* Ph  = (__half*)(PS2 + CP2_U);     // [2][PH_U]
    __shared__ float sinv[256];

    const int tid  = threadIdx.x;
    const int wid  = tid >> 5;
    const int lane = tid & 31;
    const int gid  = lane >> 2;
    const int tig  = lane & 3;
    const int bh = blockIdx.y;
    const int q0 = blockIdx.x * 256;
    const int b = bh >> 4, h = bh & 15;

    const __half* pb = eh + (size_t)bh * SEQ * SEQ;
    const float* vb = v + (size_t)bh * SEQ * HDIM;
    float* ab = attn + (size_t)bh * SEQ * SEQ;

    const int vrow = tid >> 4;            // 0..15 (+16*r)
    const int vc4  = (tid & 15) * 4;

    auto load_tile = [&](int kt, int s) {
        __half* Pd = Ph + s * PH_U;
        float*  Vd = Vs + s * CV_U;
#pragma unroll
        for (int r = 0; r < 4; r++) {
            int idx = tid + r * 256;
            int row = idx >> 2;
            int cg  = (idx & 3) * 8;      // halfs
            cpa16(&Pd[row * 32 + cg], pb + (size_t)(q0 + row) * SEQ + kt + cg);
        }
#pragma unroll
        for (int r = 0; r < 2; r++) {
            int row = vrow + r * 16;
            cpa16(&Vd[row * VSTR + vc4], vb + (size_t)(kt + row) * HDIM + vc4);
        }
    };

    load_tile(0, 0); CP_COMMIT();

    // per-row inverse sums (256 rows, one per thread)
    {
        size_t row = (size_t)bh * SEQ + q0 + tid;
        const float4* ps = (const float4*)&rowsum[row * 8];
        float4 s0 = ps[0], s1 = ps[1];
        sinv[tid] = 1.0f / (s0.x + s0.y + s0.z + s0.w + s1.x + s1.y + s1.z + s1.w);
    }

    float acc[2][8][4];
#pragma unroll
    for (int mt = 0; mt < 2; mt++)
#pragma unroll
        for (int nt = 0; nt < 8; nt++)
#pragma unroll
            for (int r = 0; r < 4; r++) acc[mt][nt][r] = 0.0f;

    int buf = 0;
    for (int kt = 0; kt < SEQ; kt += 32) {
        const int more = (kt + 32 < SEQ);
        if (more) { load_tile(kt + 32, buf ^ 1); CP_COMMIT(); }
        if (more) asm volatile("cp.async.wait_group 1;\n");
        else      asm volatile("cp.async.wait_group 0;\n");
        __syncthreads();

        // convert half tile -> fp32 P smem; fused attn writeback
        const __half* Pbh = Ph + buf * PH_U;
#pragma unroll
        for (int r = 0; r < 4; r++) {
            int idx = tid + r * 256;
            int row = idx >> 2;
            int cg  = (idx & 3) * 8;
            uint4 hv = *(const uint4*)(Pbh + row * 32 + cg);
            const __half2* hp = (const __half2*)&hv;
            float2 f0 = __half22float2(hp[0]);
            float2 f1 = __half22float2(hp[1]);
            float2 f2 = __half22float2(hp[2]);
            float2 f3 = __half22float2(hp[3]);
            float iv = sinv[row];
            float* arow = ab + (size_t)(q0 + row) * SEQ + kt + cg;
            float4 a0 = make_float4(f0.x * iv, f0.y * iv, f1.x * iv, f1.y * iv);
            float4 a1 = make_float4(f2.x * iv, f2.y * iv, f3.x * iv, f3.y * iv);
            *(float4*)arow = a0;
            *(float4*)(arow + 4) = a1;
            float* prow = &PS2[row * CSTR + cg];
            *(float4*)prow = make_float4(f0.x, f0.y, f1.x, f1.y);
            *(float4*)(prow + 4) = make_float4(f2.x, f2.y, f3.x, f3.y);
        }
        __syncthreads();

        const unsigned* Pu = (const unsigned*)PS2;
        const unsigned* Vu = (const unsigned*)(Vs + buf * CV_U);
#pragma unroll
        for (int ks = 0; ks < 4; ks++) {
            unsigned af[2][4], bf[8][2];
#pragma unroll
            for (int mt = 0; mt < 2; mt++) {
                const unsigned* p  = &Pu[(wid * 32 + mt * 16 + gid) * CSTR + ks * 8 + tig];
                const unsigned* p2 = p + 8 * CSTR;
                af[mt][0] = p[0];  af[mt][2] = p[4];
                af[mt][1] = p2[0]; af[mt][3] = p2[4];
            }
#pragma unroll
            for (int nt = 0; nt < 8; nt++) {
                const unsigned* p = &Vu[(ks * 8 + tig) * VSTR + nt * 8 + gid];
                bf[nt][0] = p[0]; bf[nt][1] = p[4 * VSTR];
            }
#pragma unroll
            for (int mt = 0; mt < 2; mt++)
#pragma unroll
                for (int nt = 0; nt < 8; nt++)
                    mma8(acc[mt][nt], af[mt], bf[nt]);
        }
        __syncthreads();
        buf ^= 1;
    }

    // epilogue: normalize output rows, round to tf32, store [B,S,D]
#pragma unroll
    for (int mt = 0; mt < 2; mt++) {
#pragma unroll
        for (int half = 0; half < 2; half++) {
            int lrow = wid * 32 + mt * 16 + gid + half * 8;
            int qrow = q0 + lrow;
            float invE = sinv[lrow];
            float* crow = ctx + ((size_t)b * SEQ + qrow) * DMODEL + h * HDIM;
#pragma unroll
            for (int nt = 0; nt < 8; nt++) {
                int d = nt * 8 + tig * 2;
                float2 o;
                o.x = rndf(acc[mt][nt][half * 2 + 0] * invE);
                o.y = rndf(acc[mt][nt][half * 2 + 1] * invE);
                *(float2*)(crow + d) = o;
            }
        }
    }
}

// -------------------- launcher ----------------------------------------------
extern "C" void kernel_launch(void* const* d_in, const int* in_sizes, int n_in,
                              void* d_out, int out_size)
{
    const float* x  = (const float*)d_in[0];
    const float* Wq = (const float*)d_in[1];
    const float* bq = (const float*)d_in[2];
    const float* Wk = (const float*)d_in[3];
    const float* bk = (const float*)d_in[4];
    const float* Wv = (const float*)d_in[5];
    const float* bv = (const float*)d_in[6];
    const float* Wo = (const float*)d_in[7];
    const float* bo = (const float*)d_in[8];

    float* out_ptr  = (float*)d_out;                                   // [B,S,D]
    float* attn_ptr = (float*)d_out + (size_t)BATCH * SEQ * DMODEL;    // [B,H,S,S]

    float *qp, *kp, *vp, *cp, *rs, *xr, *wr;
    __half* ep;
    cudaGetSymbolAddress((void**)&qp, g_q);
    cudaGetSymbolAddress((void**)&kp, g_k);
    cudaGetSymbolAddress((void**)&vp, g_v);
    cudaGetSymbolAddress((void**)&cp, g_ctx);
    cudaGetSymbolAddress((void**)&rs, g_rowsum);
    cudaGetSymbolAddress((void**)&xr, g_xr);
    cudaGetSymbolAddress((void**)&wr, g_wr);
    cudaGetSymbolAddress((void**)&ep, g_eh);

    cudaFuncSetAttribute(proj_tf32_kernel,
                         cudaFuncAttributeMaxDynamicSharedMemorySize, PROJ_SMEM_BYTES);
    cudaFuncSetAttribute(scores_tf32_kernel,
                         cudaFuncAttributeMaxDynamicSharedMemorySize, SCORES_SMEM_BYTES);
    cudaFuncSetAttribute(ctx_tf32_kernel,
                         cudaFuncAttributeMaxDynamicSharedMemorySize, CTX_SMEM_BYTES);

    dim3 blk(256);

    // pre-round inputs to tf32-representable fp32
    const size_t WSZ = (size_t)DMODEL * DMODEL;
    int xn4 = (int)((size_t)MTOT * DMODEL / 4);
    int wn4 = (int)(WSZ / 4);
    round_tf32_kernel<<<(xn4 + 255) / 256, blk>>>(xr, x, xn4);
    round_tf32_kernel<<<(wn4 + 255) / 256, blk>>>(wr + 0 * WSZ, Wq, wn4);
    round_tf32_kernel<<<(wn4 + 255) / 256, blk>>>(wr + 1 * WSZ, Wk, wn4);
    round_tf32_kernel<<<(wn4 + 255) / 256, blk>>>(wr + 2 * WSZ, Wv, wn4);
    round_tf32_kernel<<<(wn4 + 255) / 256, blk>>>(wr + 3 * WSZ, Wo, wn4);

    dim3 pgrid(DMODEL / 128, MTOT / 128);       // (8, 64)
    proj_tf32_kernel<<<pgrid, blk, PROJ_SMEM_BYTES>>>(xr, wr + 0 * WSZ, bq, qp, 1);
    proj_tf32_kernel<<<pgrid, blk, PROJ_SMEM_BYTES>>>(xr, wr + 1 * WSZ, bk, kp, 1);
    proj_tf32_kernel<<<pgrid, blk, PROJ_SMEM_BYTES>>>(xr, wr + 2 * WSZ, bv, vp, 1);

    dim3 sgrid(SEQ / 128, SEQ / 128, BATCH * HEADS);   // (8, 8, 128)
    scores_tf32_kernel<<<sgrid, blk, SCORES_SMEM_BYTES>>>(qp, kp, ep, rs);

    dim3 cgrid(SEQ / 256, BATCH * HEADS);              // (4, 128)
    ctx_tf32_kernel<<<cgrid, blk, CTX_SMEM_BYTES>>>(ep, vp, rs, attn_ptr, cp);

    proj_tf32_kernel<<<pgrid, blk, PROJ_SMEM_BYTES>>>(cp, wr + 3 * WSZ, bo, out_ptr, 0);
}

// round 11
// speedup vs baseline: 1.7868x; 1.4161x over previous
#include <cuda_runtime.h>
#include <cuda_fp16.h>
#include <math.h>

// Problem constants
#define BATCH  8
#define SEQ    1024
#define DMODEL 1024
#define HEADS  16
#define HDIM   64
#define MTOT   (BATCH * SEQ)          // 8192

// -------------------- scratch (__device__ globals; no allocs allowed) -------
__device__ __half g_qh[(size_t)BATCH * HEADS * SEQ * HDIM];   // [B,H,S,Hd]
__device__ __half g_kh[(size_t)BATCH * HEADS * SEQ * HDIM];
__device__ __half g_vt[(size_t)BATCH * HEADS * HDIM * SEQ];   // [B,H,Hd,S] (transposed)
__device__ __half g_ch[(size_t)BATCH * SEQ * DMODEL];         // ctx [B,S,D]
__device__ float  g_rowsum[(size_t)BATCH * HEADS * SEQ * 8];  // [row][kb] partial sums
__device__ __half g_xh[(size_t)MTOT * DMODEL];                // x as fp16
__device__ __half g_wh[4][(size_t)DMODEL * DMODEL];           // Wq,Wk,Wv,Wo as fp16
__device__ __half g_eh[(size_t)BATCH * HEADS * SEQ * SEQ];    // unnormalized e (fp16)

// -------------------- helpers ------------------------------------------------
__device__ __forceinline__ __half2 ex2h2(float t0, float t1) {  // {2^t0, 2^t1}
    __half2 h = __floats2half2_rn(t0, t1);
    unsigned u = *(unsigned*)&h;
    asm("ex2.approx.f16x2 %0, %0;" : "+r"(u));
    return *(__half2*)&u;
}

__device__ __forceinline__ void cpa16(void* smem, const void* gmem) {
    unsigned sa = (unsigned)__cvta_generic_to_shared(smem);
    asm volatile("cp.async.cg.shared.global [%0], [%1], 16;\n" :: "r"(sa), "l"(gmem));
}
#define CP_COMMIT() asm volatile("cp.async.commit_group;\n")

// D(16x8,f32) += A(16x16 f16, row) * B(16x8 f16, col)
__device__ __forceinline__ void mmah(float* c, const unsigned* a, const unsigned* b) {
    asm volatile(
        "mma.sync.aligned.m16n8k16.row.col.f32.f16.f16.f32 "
        "{%0,%1,%2,%3}, {%4,%5,%6,%7}, {%8,%9}, {%0,%1,%2,%3};\n"
        : "+f"(c[0]), "+f"(c[1]), "+f"(c[2]), "+f"(c[3])
        : "r"(a[0]), "r"(a[1]), "r"(a[2]), "r"(a[3]), "r"(b[0]), "r"(b[1]));
}

// =============================================================================
// fp32 -> fp16 conversion pre-pass (8 elems/thread)
// =============================================================================
__global__ __launch_bounds__(256)
void tohalf_kernel(__half* __restrict__ dst, const float* __restrict__ src, int n8)
{
    int i = blockIdx.x * blockDim.x + threadIdx.x;
    if (i < n8) {
        const float4* s = (const float4*)src + i * 2;
        float4 v0 = s[0], v1 = s[1];
        __half2 h[4];
        h[0] = __floats2half2_rn(v0.x, v0.y);
        h[1] = __floats2half2_rn(v0.z, v0.w);
        h[2] = __floats2half2_rn(v1.x, v1.y);
        h[3] = __floats2half2_rn(v1.z, v1.w);
        *(uint4*)(dst + (size_t)i * 8) = *(uint4*)h;
    }
}

// =============================================================================
// Projection GEMM (fp16): C = A[M,1024] * W[1024,1024]^T + bias
// BM=128, BN=128, BK=32; 8 warps, warp tile 64x32; 3-stage cp.async.
// mode 0: fp32 out row-major; mode 1: fp16 out split-heads [bh][s][d];
// mode 2: fp16 out V^T [bh][d][s].
// =============================================================================
#define PH_STR 40                       // halfs; word stride 20 -> conflict-free
#define PH_TILE (128 * PH_STR)          // halfs per tile
#define PH_NT (DMODEL / 32)             // 32 k-tiles
#define PROJ_SMEM_BYTES (3 * 2 * PH_TILE * 2)   // 61440

__global__ __launch_bounds__(256, 2)
void proj_h_kernel(const __half* __restrict__ A, const __half* __restrict__ W,
                   const float* __restrict__ bias, float* __restrict__ Cf,
                   __half* __restrict__ Ch, int mode)
{
    extern __shared__ __half hsm[];

    const int tid  = threadIdx.x;
    const int wid  = tid >> 5;
    const int lane = tid & 31;
    const int gid  = lane >> 2;
    const int t2   = (lane & 3) * 2;
    const int m0 = blockIdx.y * 128;
    const int n0 = blockIdx.x * 128;
    const int wm = (wid >> 2) * 64;
    const int wn = (wid & 3) * 32;

    float acc[4][4][4];
#pragma unroll
    for (int mt = 0; mt < 4; mt++)
#pragma unroll
        for (int nt = 0; nt < 4; nt++)
#pragma unroll
            for (int r = 0; r < 4; r++) acc[mt][nt][r] = 0.0f;

    auto load_tile = [&](int kt, int s) {
        __half* As = hsm + s * 2 * PH_TILE;
        __half* Bs = As + PH_TILE;
#pragma unroll
        for (int r = 0; r < 2; r++) {
            int idx = tid + r * 256;          // 0..511
            int row = idx >> 2;               // 0..127
            int c   = (idx & 3) * 8;          // halfs
            cpa16(&As[row * PH_STR + c], A + (size_t)(m0 + row) * DMODEL + kt + c);
            cpa16(&Bs[row * PH_STR + c], W + (size_t)(n0 + row) * DMODEL + kt + c);
        }
    };

    load_tile(0, 0); CP_COMMIT();
    load_tile(32, 1); CP_COMMIT();

    for (int t = 0; t < PH_NT; t++) {
        if (t + 2 < PH_NT) { load_tile((t + 2) * 32, (t + 2) % 3); CP_COMMIT(); }
        if (t + 2 < PH_NT)      asm volatile("cp.async.wait_group 2;\n");
        else if (t + 1 < PH_NT) asm volatile("cp.async.wait_group 1;\n");
        else                    asm volatile("cp.async.wait_group 0;\n");
        __syncthreads();

        const __half* Ab = hsm + (t % 3) * 2 * PH_TILE;
        const __half* Bb = Ab + PH_TILE;
#pragma unroll
        for (int ks = 0; ks < 2; ks++) {
            unsigned af[4][4], bf[4][2];
#pragma unroll
            for (int mt = 0; mt < 4; mt++) {
                const __half* p  = &Ab[(wm + mt * 16 + gid) * PH_STR + ks * 16 + t2];
                const __half* p2 = p + 8 * PH_STR;
                af[mt][0] = *(const unsigned*)p;
                af[mt][1] = *(const unsigned*)p2;
                af[mt][2] = *(const unsigned*)(p + 8);
                af[mt][3] = *(const unsigned*)(p2 + 8);
            }
#pragma unroll
            for (int nt = 0; nt < 4; nt++) {
                const __half* p = &Bb[(wn + nt * 8 + gid) * PH_STR + ks * 16 + t2];
                bf[nt][0] = *(const unsigned*)p;
                bf[nt][1] = *(const unsigned*)(p + 8);
            }
#pragma unroll
            for (int mt = 0; mt < 4; mt++)
#pragma unroll
                for (int nt = 0; nt < 4; nt++)
                    mmah(acc[mt][nt], af[mt], bf[nt]);
        }
        __syncthreads();
    }

#pragma unroll
    for (int mt = 0; mt < 4; mt++) {
#pragma unroll
        for (int hf = 0; hf < 2; hf++) {
            int m  = m0 + wm + mt * 16 + gid + hf * 8;
            int bb = m >> 10;
            int s  = m & 1023;
#pragma unroll
            for (int nt = 0; nt < 4; nt++) {
                int n = n0 + wn + nt * 8 + t2;
                float vx = acc[mt][nt][hf * 2 + 0] + bias[n];
                float vy = acc[mt][nt][hf * 2 + 1] + bias[n + 1];
                if (mode == 0) {
                    float2 v; v.x = vx; v.y = vy;
                    *(float2*)(Cf + (size_t)m * DMODEL + n) = v;
                } else if (mode == 1) {
                    int h = n >> 6, d = n & 63;
                    size_t idx = ((((size_t)bb * HEADS + h) * SEQ + s) << 6) + d;
                    *(__half2*)(Ch + idx) = __floats2half2_rn(vx, vy);
                } else {
                    int h = n >> 6, d = n & 63;
                    size_t base = (((size_t)bb * HEADS + h) * HDIM + d) * SEQ + s;
                    Ch[base]       = __float2half_rn(vx);
                    Ch[base + SEQ] = __float2half_rn(vy);
                }
            }
        }
    }
}

// =============================================================================
// Scores (fp16): e = fp16(2^(s*0.125*log2e)) into g_eh + per-block rowsums.
// Tiles 128x128, K=64; per (b,h); one-shot smem.
// =============================================================================
#define SH_STR 72                       // halfs; word stride 36 -> conflict-free
#define SH_TILE (128 * SH_STR)
#define SCORES_SMEM_BYTES (2 * SH_TILE * 2)   // 36864
#define SCALE_LOG2E 0.18033688f

__global__ __launch_bounds__(256, 2)
void scores_h_kernel(const __half* __restrict__ q, const __half* __restrict__ k,
                     __half* __restrict__ eh, float* __restrict__ rowsum)
{
    extern __shared__ __half ssm[];
    __half* Qs = ssm;                 // [128][SH_STR]
    __half* Ks = ssm + SH_TILE;
    __shared__ float sexp[128];

    const int tid  = threadIdx.x;
    const int wid  = tid >> 5;
    const int lane = tid & 31;
    const int gid  = lane >> 2;
    const int t2   = (lane & 3) * 2;
    const int bh = blockIdx.z;
    const int q0 = blockIdx.y * 128;
    const int k0 = blockIdx.x * 128;
    const int kb = blockIdx.x;
    const int wm = (wid >> 2) * 64;
    const int wn = (wid & 3) * 32;

    const __half* qb = q + (size_t)bh * SEQ * HDIM;
    const __half* kp = k + (size_t)bh * SEQ * HDIM;

#pragma unroll
    for (int r = 0; r < 4; r++) {
        int idx = tid + r * 256;          // 0..1023
        int row = idx >> 3;               // 0..127
        int c   = (idx & 7) * 8;          // halfs 0..56
        cpa16(&Qs[row * SH_STR + c], qb + (size_t)(q0 + row) * HDIM + c);
        cpa16(&Ks[row * SH_STR + c], kp + (size_t)(k0 + row) * HDIM + c);
    }
    CP_COMMIT();
    if (tid < 128) sexp[tid] = 0.0f;
    asm volatile("cp.async.wait_group 0;\n");
    __syncthreads();

    float acc[4][4][4];
#pragma unroll
    for (int mt = 0; mt < 4; mt++)
#pragma unroll
        for (int nt = 0; nt < 4; nt++)
#pragma unroll
            for (int r = 0; r < 4; r++) acc[mt][nt][r] = 0.0f;

#pragma unroll
    for (int ks = 0; ks < 4; ks++) {
        unsigned af[4][4], bf[4][2];
#pragma unroll
        for (int mt = 0; mt < 4; mt++) {
            const __half* p  = &Qs[(wm + mt * 16 + gid) * SH_STR + ks * 16 + t2];
            const __half* p2 = p + 8 * SH_STR;
            af[mt][0] = *(const unsigned*)p;
            af[mt][1] = *(const unsigned*)p2;
            af[mt][2] = *(const unsigned*)(p + 8);
            af[mt][3] = *(const unsigned*)(p2 + 8);
        }
#pragma unroll
        for (int nt = 0; nt < 4; nt++) {
            const __half* p = &Ks[(wn + nt * 8 + gid) * SH_STR + ks * 16 + t2];
            bf[nt][0] = *(const unsigned*)p;
            bf[nt][1] = *(const unsigned*)(p + 8);
        }
#pragma unroll
        for (int mt = 0; mt < 4; mt++)
#pragma unroll
            for (int nt = 0; nt < 4; nt++)
                mmah(acc[mt][nt], af[mt], bf[nt]);
    }

    __half* eb = eh + (size_t)bh * SEQ * SEQ;
#pragma unroll
    for (int mt = 0; mt < 4; mt++) {
#pragma unroll
        for (int hf = 0; hf < 2; hf++) {
            int lr = wm + mt * 16 + gid + hf * 8;
            int sq = q0 + lr;
            float lsum = 0.0f;
#pragma unroll
            for (int nt = 0; nt < 4; nt++) {
                int sk = k0 + wn + nt * 8 + t2;
                __half2 e2 = ex2h2(acc[mt][nt][hf * 2 + 0] * SCALE_LOG2E,
                                   acc[mt][nt][hf * 2 + 1] * SCALE_LOG2E);
                *(__half2*)(eb + (size_t)sq * SEQ + sk) = e2;
                float2 ef = __half22float2(e2);
                lsum += ef.x + ef.y;
            }
            lsum += __shfl_xor_sync(0xffffffffu, lsum, 1);
            lsum += __shfl_xor_sync(0xffffffffu, lsum, 2);
            if ((lane & 3) == 0) atomicAdd(&sexp[lr], lsum);
        }
    }
    __syncthreads();
    if (tid < 128)
        rowsum[((size_t)bh * SEQ + q0 + tid) * 8 + kb] = sexp[tid];
}

// =============================================================================
// Context (fp16): P = e (half, direct), B = V^T tiles. Writes final attn
// (fp32, normalized) and ctx (fp16, [B,S,D], output-normalized).
// BM=256, N=64, BK=32; 8 warps; 2-stage cp.async.
// =============================================================================
#define CPH_STR 40
#define CVH_STR 40
#define CPH_TILE (256 * CPH_STR)        // halfs
#define CVH_TILE (64 * CVH_STR)
#define CTX_SMEM_BYTES (2 * (CPH_TILE + CVH_TILE) * 2)   // 51200

__global__ __launch_bounds__(256, 2)
void ctx_h_kernel(const __half* __restrict__ eh, const __half* __restrict__ vt,
                  const float* __restrict__ rowsum, float* __restrict__ attn,
                  __half* __restrict__ ctx)
{
    extern __shared__ __half csm[];
    __half* Ps = csm;                     // [2][CPH_TILE]
    __half* Vs = csm + 2 * CPH_TILE;      // [2][CVH_TILE]
    __shared__ float sinv[256];

    const int tid  = threadIdx.x;
    const int wid  = tid >> 5;
    const int lane = tid & 31;
    const int gid  = lane >> 2;
    const int t2   = (lane & 3) * 2;
    const int bh = blockIdx.y;
    const int q0 = blockIdx.x * 256;
    const int b = bh >> 4, h = bh & 15;

    const __half* pb  = eh + (size_t)bh * SEQ * SEQ;
    const __half* vtb = vt + (size_t)bh * HDIM * SEQ;
    float* ab = attn + (size_t)bh * SEQ * SEQ;

    auto load_tile = [&](int kt, int s) {
        __half* Pd = Ps + s * CPH_TILE;
        __half* Vd = Vs + s * CVH_TILE;
#pragma unroll
        for (int r = 0; r < 4; r++) {
            int idx = tid + r * 256;        // 0..1023
            int row = idx >> 2;             // 0..255
            int c   = (idx & 3) * 8;        // halfs 0..24
            cpa16(&Pd[row * CPH_STR + c], pb + (size_t)(q0 + row) * SEQ + kt + c);
        }
        {
            int row = tid >> 2;             // 0..63
            int c   = (tid & 3) * 8;
            cpa16(&Vd[row * CVH_STR + c], vtb + (size_t)row * SEQ + kt + c);
        }
    };

    load_tile(0, 0); CP_COMMIT();

    {
        size_t row = (size_t)bh * SEQ + q0 + tid;
        const float4* ps = (const float4*)&rowsum[row * 8];
        float4 s0 = ps[0], s1 = ps[1];
        sinv[tid] = 1.0f / (s0.x + s0.y + s0.z + s0.w + s1.x + s1.y + s1.z + s1.w);
    }

    float acc[2][8][4];
#pragma unroll
    for (int mt = 0; mt < 2; mt++)
#pragma unroll
        for (int nt = 0; nt < 8; nt++)
#pragma unroll
            for (int r = 0; r < 4; r++) acc[mt][nt][r] = 0.0f;

    int buf = 0;
    for (int kt = 0; kt < SEQ; kt += 32) {
        const int more = (kt + 32 < SEQ);
        if (more) { load_tile(kt + 32, buf ^ 1); CP_COMMIT(); }
        if (more) asm volatile("cp.async.wait_group 1;\n");
        else      asm volatile("cp.async.wait_group 0;\n");
        __syncthreads();

        const __half* Pd = Ps + buf * CPH_TILE;
        const __half* Vd = Vs + buf * CVH_TILE;

        // attn writeback: p = e*inv (fp32), from half smem tile
#pragma unroll
        for (int r = 0; r < 4; r++) {
            int idx = tid + r * 256;
            int row = idx >> 2;
            int c   = (idx & 3) * 8;
            uint4 hv = *(const uint4*)(Pd + row * CPH_STR + c);
            const __half2* hp = (const __half2*)&hv;
            float2 f0 = __half22float2(hp[0]);
            float2 f1 = __half22float2(hp[1]);
            float2 f2 = __half22float2(hp[2]);
            float2 f3 = __half22float2(hp[3]);
            float iv = sinv[row];
            float* arow = ab + (size_t)(q0 + row) * SEQ + kt + c;
            *(float4*)arow       = make_float4(f0.x * iv, f0.y * iv, f1.x * iv, f1.y * iv);
            *(float4*)(arow + 4) = make_float4(f2.x * iv, f2.y * iv, f3.x * iv, f3.y * iv);
        }

#pragma unroll
        for (int ks = 0; ks < 2; ks++) {
            unsigned af[2][4], bf[8][2];
#pragma unroll
            for (int mt = 0; mt < 2; mt++) {
                const __half* p  = &Pd[(wid * 32 + mt * 16 + gid) * CPH_STR + ks * 16 + t2];
                const __half* p2 = p + 8 * CPH_STR;
                af[mt][0] = *(const unsigned*)p;
                af[mt][1] = *(const unsigned*)p2;
                af[mt][2] = *(const unsigned*)(p + 8);
                af[mt][3] = *(const unsigned*)(p2 + 8);
            }
#pragma unroll
            for (int nt = 0; nt < 8; nt++) {
                const __half* p = &Vd[(nt * 8 + gid) * CVH_STR + ks * 16 + t2];
                bf[nt][0] = *(const unsigned*)p;
                bf[nt][1] = *(const unsigned*)(p + 8);
            }
#pragma unroll
            for (int mt = 0; mt < 2; mt++)
#pragma unroll
                for (int nt = 0; nt < 8; nt++)
                    mmah(acc[mt][nt], af[mt], bf[nt]);
        }
        __syncthreads();
        buf ^= 1;
    }

    // epilogue: ctx = fp16(acc * inv), layout [B,S,D]
#pragma unroll
    for (int mt = 0; mt < 2; mt++) {
#pragma unroll
        for (int hf = 0; hf < 2; hf++) {
            int lrow = wid * 32 + mt * 16 + gid + hf * 8;
            int qrow = q0 + lrow;
            float invE = sinv[lrow];
            __half* crow = ctx + ((size_t)b * SEQ + qrow) * DMODEL + h * HDIM;
#pragma unroll
            for (int nt = 0; nt < 8; nt++) {
                int d = nt * 8 + t2;
                *(__half2*)(crow + d) = __floats2half2_rn(acc[mt][nt][hf * 2 + 0] * invE,
                                                          acc[mt][nt][hf * 2 + 1] * invE);
            }
        }
    }
}

// -------------------- launcher ----------------------------------------------
extern "C" void kernel_launch(void* const* d_in, const int* in_sizes, int n_in,
                              void* d_out, int out_size)
{
    const float* x  = (const float*)d_in[0];
    const float* Wq = (const float*)d_in[1];
    const float* bq = (const float*)d_in[2];
    const float* Wk = (const float*)d_in[3];
    const float* bk = (const float*)d_in[4];
    const float* Wv = (const float*)d_in[5];
    const float* bv = (const float*)d_in[6];
    const float* Wo = (const float*)d_in[7];
    const float* bo = (const float*)d_in[8];

    float* out_ptr  = (float*)d_out;                                   // [B,S,D]
    float* attn_ptr = (float*)d_out + (size_t)BATCH * SEQ * DMODEL;    // [B,H,S,S]

    __half *qp, *kp, *vtp, *cp, *xh, *wh, *ep;
    float *rs;
    cudaGetSymbolAddress((void**)&qp, g_qh);
    cudaGetSymbolAddress((void**)&kp, g_kh);
    cudaGetSymbolAddress((void**)&vtp, g_vt);
    cudaGetSymbolAddress((void**)&cp, g_ch);
    cudaGetSymbolAddress((void**)&rs, g_rowsum);
    cudaGetSymbolAddress((void**)&xh, g_xh);
    cudaGetSymbolAddress((void**)&wh, g_wh);
    cudaGetSymbolAddress((void**)&ep, g_eh);

    cudaFuncSetAttribute(proj_h_kernel,
                         cudaFuncAttributeMaxDynamicSharedMemorySize, PROJ_SMEM_BYTES);
    cudaFuncSetAttribute(scores_h_kernel,
                         cudaFuncAttributeMaxDynamicSharedMemorySize, SCORES_SMEM_BYTES);
    cudaFuncSetAttribute(ctx_h_kernel,
                         cudaFuncAttributeMaxDynamicSharedMemorySize, CTX_SMEM_BYTES);

    dim3 blk(256);

    // fp32 -> fp16 conversion of inputs
    const size_t WSZ = (size_t)DMODEL * DMODEL;
    int xn8 = (int)((size_t)MTOT * DMODEL / 8);
    int wn8 = (int)(WSZ / 8);
    tohalf_kernel<<<(xn8 + 255) / 256, blk>>>(xh, x, xn8);
    tohalf_kernel<<<(wn8 + 255) / 256, blk>>>(wh + 0 * WSZ, Wq, wn8);
    tohalf_kernel<<<(wn8 + 255) / 256, blk>>>(wh + 1 * WSZ, Wk, wn8);
    tohalf_kernel<<<(wn8 + 255) / 256, blk>>>(wh + 2 * WSZ, Wv, wn8);
    tohalf_kernel<<<(wn8 + 255) / 256, blk>>>(wh + 3 * WSZ, Wo, wn8);

    dim3 pgrid(DMODEL / 128, MTOT / 128);       // (8, 64)
    proj_h_kernel<<<pgrid, blk, PROJ_SMEM_BYTES>>>(xh, wh + 0 * WSZ, bq, nullptr, qp, 1);
    proj_h_kernel<<<pgrid, blk, PROJ_SMEM_BYTES>>>(xh, wh + 1 * WSZ, bk, nullptr, kp, 1);
    proj_h_kernel<<<pgrid, blk, PROJ_SMEM_BYTES>>>(xh, wh + 2 * WSZ, bv, nullptr, vtp, 2);

    dim3 sgrid(SEQ / 128, SEQ / 128, BATCH * HEADS);   // (8, 8, 128)
    scores_h_kernel<<<sgrid, blk, SCORES_SMEM_BYTES>>>(qp, kp, ep, rs);

    dim3 cgrid(SEQ / 256, BATCH * HEADS);              // (4, 128)
    ctx_h_kernel<<<cgrid, blk, CTX_SMEM_BYTES>>>(ep, vtp, rs, attn_ptr, cp);

    proj_h_kernel<<<pgrid, blk, PROJ_SMEM_BYTES>>>(cp, wh + 3 * WSZ, bo, out_ptr, nullptr, 0);
}

// round 13
// speedup vs baseline: 1.8630x; 1.0426x over previous
#include <cuda_runtime.h>
#include <cuda_fp16.h>
#include <math.h>

// Problem constants
#define BATCH  8
#define SEQ    1024
#define DMODEL 1024
#define HEADS  16
#define HDIM   64
#define MTOT   (BATCH * SEQ)          // 8192

// -------------------- scratch (__device__ globals; no allocs allowed) -------
__device__ __half g_qh[(size_t)BATCH * HEADS * SEQ * HDIM];   // [B,H,S,Hd]
__device__ __half g_kh[(size_t)BATCH * HEADS * SEQ * HDIM];
__device__ __half g_vt[(size_t)BATCH * HEADS * HDIM * SEQ];   // [B,H,Hd,S]
__device__ __half g_ch[(size_t)BATCH * SEQ * DMODEL];         // ctx [B,S,D]
__device__ float  g_rowsum[(size_t)BATCH * HEADS * SEQ * 8];
__device__ __half g_xh[(size_t)MTOT * DMODEL];
__device__ __half g_wh[4][(size_t)DMODEL * DMODEL];
__device__ __half g_eh[(size_t)BATCH * HEADS * SEQ * SEQ];

// -------------------- helpers ------------------------------------------------
__device__ __forceinline__ __half2 ex2h2(float t0, float t1) {
    __half2 h = __floats2half2_rn(t0, t1);
    unsigned u = *(unsigned*)&h;
    asm("ex2.approx.f16x2 %0, %0;" : "+r"(u));
    return *(__half2*)&u;
}

__device__ __forceinline__ void cpa16(void* smem, const void* gmem) {
    unsigned sa = (unsigned)__cvta_generic_to_shared(smem);
    asm volatile("cp.async.cg.shared.global [%0], [%1], 16;\n" :: "r"(sa), "l"(gmem));
}
#define CP_COMMIT() asm volatile("cp.async.commit_group;\n")

__device__ __forceinline__ unsigned s2u(const void* p) {
    unsigned a;
    asm("{ .reg .u64 t; cvta.to.shared.u64 t, %1; cvt.u32.u64 %0, t; }" : "=r"(a) : "l"(p));
    return a;
}

// ldmatrix x4: four 8x8 b16 matrices; lane groups of 8 give row addresses.
__device__ __forceinline__ void ldsm4(unsigned* r, unsigned addr) {
    asm volatile("ldmatrix.sync.aligned.m8n8.x4.shared.b16 {%0,%1,%2,%3}, [%4];"
                 : "=r"(r[0]), "=r"(r[1]), "=r"(r[2]), "=r"(r[3]) : "r"(addr));
}

// D(16x8,f32) += A(16x16 f16, row) * B(16x8 f16, col)
__device__ __forceinline__ void mmah(float* c, const unsigned* a, const unsigned* b) {
    asm volatile(
        "mma.sync.aligned.m16n8k16.row.col.f32.f16.f16.f32 "
        "{%0,%1,%2,%3}, {%4,%5,%6,%7}, {%8,%9}, {%0,%1,%2,%3};\n"
        : "+f"(c[0]), "+f"(c[1]), "+f"(c[2]), "+f"(c[3])
        : "r"(a[0]), "r"(a[1]), "r"(a[2]), "r"(a[3]), "r"(b[0]), "r"(b[1]));
}

// =============================================================================
// fp32 -> fp16 conversion pre-pass (8 elems/thread)
// =============================================================================
__global__ __launch_bounds__(256)
void tohalf_kernel(__half* __restrict__ dst, const float* __restrict__ src, int n8)
{
    int i = blockIdx.x * blockDim.x + threadIdx.x;
    if (i < n8) {
        const float4* s = (const float4*)src + i * 2;
        float4 v0 = s[0], v1 = s[1];
        __half2 h[4];
        h[0] = __floats2half2_rn(v0.x, v0.y);
        h[1] = __floats2half2_rn(v0.z, v0.w);
        h[2] = __floats2half2_rn(v1.x, v1.y);
        h[3] = __floats2half2_rn(v1.z, v1.w);
        *(uint4*)(dst + (size_t)i * 8) = *(uint4*)h;
    }
}

// =============================================================================
// Projection GEMM (fp16 mma.sync + ldmatrix): C = A[M,1024]*W[1024,1024]^T + b
// BM=128, BN=128, BK=32; 8 warps, warp tile 64x32; 3-stage cp.async.
// mode 0: fp32 row-major; mode 1: fp16 split-heads; mode 2: fp16 V^T.
// =============================================================================
#define PH_STR 40                       // halfs; word stride 20 -> conflict-free
#define PH_TILE (128 * PH_STR)          // halfs per tile
#define PH_NT (DMODEL / 32)             // 32 k-tiles
#define PROJ_SMEM_BYTES (3 * 2 * PH_TILE * 2)   // 61440

__global__ __launch_bounds__(256, 2)
void proj_h_kernel(const __half* __restrict__ A, const __half* __restrict__ W,
                   const float* __restrict__ bias, float* __restrict__ Cf,
                   __half* __restrict__ Ch, int mode)
{
    extern __shared__ __half hsm[];

    const int tid  = threadIdx.x;
    const int wid  = tid >> 5;
    const int lane = tid & 31;
    const int gid  = lane >> 2;
    const int t2   = (lane & 3) * 2;
    const int m0 = blockIdx.y * 128;
    const int n0 = blockIdx.x * 128;
    const int wm = (wid >> 2) * 64;
    const int wn = (wid & 3) * 32;

    const unsigned hb = s2u(hsm);
    const int quad = lane >> 3, win = lane & 7;
    // ldmatrix lane offsets (bytes): A groups (row,k): (0,0)(8,0)(0,8)(8,8)
    const unsigned aL = (unsigned)((win + (quad & 1) * 8) * PH_STR * 2 + (quad >> 1) * 16);
    // B groups (n,k): (0,0)(0,8)(8,0)(8,8)
    const unsigned bL = (unsigned)((win + (quad >> 1) * 8) * PH_STR * 2 + (quad & 1) * 16);

    float acc[4][4][4];
#pragma unroll
    for (int mt = 0; mt < 4; mt++)
#pragma unroll
        for (int nt = 0; nt < 4; nt++)
#pragma unroll
            for (int r = 0; r < 4; r++) acc[mt][nt][r] = 0.0f;

    auto load_tile = [&](int kt, int s) {
        __half* As = hsm + s * 2 * PH_TILE;
        __half* Bs = As + PH_TILE;
#pragma unroll
        for (int r = 0; r < 2; r++) {
            int idx = tid + r * 256;          // 0..511
            int row = idx >> 2;               // 0..127
            int c   = (idx & 3) * 8;          // halfs
            cpa16(&As[row * PH_STR + c], A + (size_t)(m0 + row) * DMODEL + kt + c);
            cpa16(&Bs[row * PH_STR + c], W + (size_t)(n0 + row) * DMODEL + kt + c);
        }
    };

    load_tile(0, 0); CP_COMMIT();
    load_tile(32, 1); CP_COMMIT();

    for (int t = 0; t < PH_NT; t++) {
        if (t + 2 < PH_NT) { load_tile((t + 2) * 32, (t + 2) % 3); CP_COMMIT(); }
        if (t + 2 < PH_NT)      asm volatile("cp.async.wait_group 2;\n");
        else if (t + 1 < PH_NT) asm volatile("cp.async.wait_group 1;\n");
        else                    asm volatile("cp.async.wait_group 0;\n");
        __syncthreads();

        const unsigned ab = hb + (unsigned)((t % 3) * (2 * PH_TILE * 2));
        const unsigned bb = ab + PH_TILE * 2;
#pragma unroll
        for (int ks = 0; ks < 2; ks++) {
            unsigned af[4][4], bf[4][2];
#pragma unroll
            for (int mt = 0; mt < 4; mt++)
                ldsm4(af[mt], ab + (unsigned)((wm + mt * 16) * PH_STR * 2 + ks * 32) + aL);
#pragma unroll
            for (int np = 0; np < 2; np++) {
                unsigned t4[4];
                ldsm4(t4, bb + (unsigned)((wn + np * 16) * PH_STR * 2 + ks * 32) + bL);
                bf[np * 2][0] = t4[0]; bf[np * 2][1] = t4[1];
                bf[np * 2 + 1][0] = t4[2]; bf[np * 2 + 1][1] = t4[3];
            }
#pragma unroll
            for (int mt = 0; mt < 4; mt++)
#pragma unroll
                for (int nt = 0; nt < 4; nt++)
                    mmah(acc[mt][nt], af[mt], bf[nt]);
        }
        __syncthreads();
    }

#pragma unroll
    for (int mt = 0; mt < 4; mt++) {
#pragma unroll
        for (int hf = 0; hf < 2; hf++) {
            int m  = m0 + wm + mt * 16 + gid + hf * 8;
            int bb2 = m >> 10;
            int s  = m & 1023;
#pragma unroll
            for (int nt = 0; nt < 4; nt++) {
                int n = n0 + wn + nt * 8 + t2;
                float vx = acc[mt][nt][hf * 2 + 0] + bias[n];
                float vy = acc[mt][nt][hf * 2 + 1] + bias[n + 1];
                if (mode == 0) {
                    float2 v; v.x = vx; v.y = vy;
                    *(float2*)(Cf + (size_t)m * DMODEL + n) = v;
                } else if (mode == 1) {
                    int h = n >> 6, d = n & 63;
                    size_t idx = ((((size_t)bb2 * HEADS + h) * SEQ + s) << 6) + d;
                    *(__half2*)(Ch + idx) = __floats2half2_rn(vx, vy);
                } else {
                    int h = n >> 6, d = n & 63;
                    size_t base = (((size_t)bb2 * HEADS + h) * HDIM + d) * SEQ + s;
                    Ch[base]       = __float2half_rn(vx);
                    Ch[base + SEQ] = __float2half_rn(vy);
                }
            }
        }
    }
}

// =============================================================================
// Scores (fp16 mma.sync + ldmatrix): e = fp16(2^(s*0.125*log2e)) + rowsums.
// Tiles 128x128, K=64; per (b,h); one-shot smem.
// =============================================================================
#define SH_STR 72                       // halfs; word stride 36 -> conflict-free
#define SH_TILE (128 * SH_STR)
#define SCORES_SMEM_BYTES (2 * SH_TILE * 2)   // 36864
#define SCALE_LOG2E 0.18033688f

__global__ __launch_bounds__(256, 2)
void scores_h_kernel(const __half* __restrict__ q, const __half* __restrict__ k,
                     __half* __restrict__ eh, float* __restrict__ rowsum)
{
    extern __shared__ __half ssm[];
    __half* Qs = ssm;                 // [128][SH_STR]
    __half* Ks = ssm + SH_TILE;
    __shared__ float sexp[128];

    const int tid  = threadIdx.x;
    const int wid  = tid >> 5;
    const int lane = tid & 31;
    const int gid  = lane >> 2;
    const int t2   = (lane & 3) * 2;
    const int bh = blockIdx.z;
    const int q0 = blockIdx.y * 128;
    const int k0 = blockIdx.x * 128;
    const int kb = blockIdx.x;
    const int wm = (wid >> 2) * 64;
    const int wn = (wid & 3) * 32;

    const unsigned qbs = s2u(ssm);
    const unsigned kbs = qbs + SH_TILE * 2;
    const int quad = lane >> 3, win = lane & 7;
    const unsigned aL = (unsigned)((win + (quad & 1) * 8) * SH_STR * 2 + (quad >> 1) * 16);
    const unsigned bL = (unsigned)((win + (quad >> 1) * 8) * SH_STR * 2 + (quad & 1) * 16);

    const __half* qb = q + (size_t)bh * SEQ * HDIM;
    const __half* kp = k + (size_t)bh * SEQ * HDIM;

#pragma unroll
    for (int r = 0; r < 4; r++) {
        int idx = tid + r * 256;          // 0..1023
        int row = idx >> 3;               // 0..127
        int c   = (idx & 7) * 8;          // halfs 0..56
        cpa16(&Qs[row * SH_STR + c], qb + (size_t)(q0 + row) * HDIM + c);
        cpa16(&Ks[row * SH_STR + c], kp + (size_t)(k0 + row) * HDIM + c);
    }
    CP_COMMIT();
    if (tid < 128) sexp[tid] = 0.0f;
    asm volatile("cp.async.wait_group 0;\n");
    __syncthreads();

    float acc[4][4][4];
#pragma unroll
    for (int mt = 0; mt < 4; mt++)
#pragma unroll
        for (int nt = 0; nt < 4; nt++)
#pragma unroll
            for (int r = 0; r < 4; r++) acc[mt][nt][r] = 0.0f;

#pragma unroll
    for (int ks = 0; ks < 4; ks++) {
        unsigned af[4][4], bf[4][2];
#pragma unroll
        for (int mt = 0; mt < 4; mt++)
            ldsm4(af[mt], qbs + (unsigned)((wm + mt * 16) * SH_STR * 2 + ks * 32) + aL);
#pragma unroll
        for (int np = 0; np < 2; np++) {
            unsigned t4[4];
            ldsm4(t4, kbs + (unsigned)((wn + np * 16) * SH_STR * 2 + ks * 32) + bL);
            bf[np * 2][0] = t4[0]; bf[np * 2][1] = t4[1];
            bf[np * 2 + 1][0] = t4[2]; bf[np * 2 + 1][1] = t4[3];
        }
#pragma unroll
        for (int mt = 0; mt < 4; mt++)
#pragma unroll
            for (int nt = 0; nt < 4; nt++)
                mmah(acc[mt][nt], af[mt], bf[nt]);
    }

    __half* eb = eh + (size_t)bh * SEQ * SEQ;
#pragma unroll
    for (int mt = 0; mt < 4; mt++) {
#pragma unroll
        for (int hf = 0; hf < 2; hf++) {
            int lr = wm + mt * 16 + gid + hf * 8;
            int sq = q0 + lr;
            float lsum = 0.0f;
#pragma unroll
            for (int nt = 0; nt < 4; nt++) {
                int sk = k0 + wn + nt * 8 + t2;
                __half2 e2 = ex2h2(acc[mt][nt][hf * 2 + 0] * SCALE_LOG2E,
                                   acc[mt][nt][hf * 2 + 1] * SCALE_LOG2E);
                *(__half2*)(eb + (size_t)sq * SEQ + sk) = e2;
                float2 ef = __half22float2(e2);
                lsum += ef.x + ef.y;
            }
            lsum += __shfl_xor_sync(0xffffffffu, lsum, 1);
            lsum += __shfl_xor_sync(0xffffffffu, lsum, 2);
            if ((lane & 3) == 0) atomicAdd(&sexp[lr], lsum);
        }
    }
    __syncthreads();
    if (tid < 128)
        rowsum[((size_t)bh * SEQ + q0 + tid) * 8 + kb] = sexp[tid];
}

// =============================================================================
// Context (fp16 mma.sync + ldmatrix): P = e direct, B = V^T tiles. Writes
// final attn (fp32, normalized) and ctx (fp16, [B,S,D], output-normalized).
// BM=256, N=64, BK=32; 8 warps; 2-stage cp.async.
// =============================================================================
#define CPH_STR 40
#define CVH_STR 40
#define CPH_TILE (256 * CPH_STR)        // halfs
#define CVH_TILE (64 * CVH_STR)
#define CTX_SMEM_BYTES (2 * (CPH_TILE + CVH_TILE) * 2)   // 51200

__global__ __launch_bounds__(256, 2)
void ctx_h_kernel(const __half* __restrict__ eh, const __half* __restrict__ vt,
                  const float* __restrict__ rowsum, float* __restrict__ attn,
                  __half* __restrict__ ctx)
{
    extern __shared__ __half csm[];
    __half* Ps = csm;                     // [2][CPH_TILE]
    __half* Vs = csm + 2 * CPH_TILE;      // [2][CVH_TILE]
    __shared__ float sinv[256];

    const int tid  = threadIdx.x;
    const int wid  = tid >> 5;
    const int lane = tid & 31;
    const int gid  = lane >> 2;
    const int t2   = (lane & 3) * 2;
    const int bh = blockIdx.y;
    const int q0 = blockIdx.x * 256;
    const int b = bh >> 4, h = bh & 15;

    const unsigned pbs = s2u(csm);
    const unsigned vbs = pbs + 2 * CPH_TILE * 2;
    const int quad = lane >> 3, win = lane & 7;
    const unsigned aL = (unsigned)((win + (quad & 1) * 8) * CPH_STR * 2 + (quad >> 1) * 16);
    const unsigned bL = (unsigned)((win + (quad >> 1) * 8) * CVH_STR * 2 + (quad & 1) * 16);

    const __half* pb  = eh + (size_t)bh * SEQ * SEQ;
    const __half* vtb = vt + (size_t)bh * HDIM * SEQ;
    float* ab = attn + (size_t)bh * SEQ * SEQ;

    auto load_tile = [&](int kt, int s) {
        __half* Pd = Ps + s * CPH_TILE;
        __half* Vd = Vs + s * CVH_TILE;
#pragma unroll
        for (int r = 0; r < 4; r++) {
            int idx = tid + r * 256;
            int row = idx >> 2;
            int c   = (idx & 3) * 8;
            cpa16(&Pd[row * CPH_STR + c], pb + (size_t)(q0 + row) * SEQ + kt + c);
        }
        {
            int row = tid >> 2;
            int c   = (tid & 3) * 8;
            cpa16(&Vd[row * CVH_STR + c], vtb + (size_t)row * SEQ + kt + c);
        }
    };

    load_tile(0, 0); CP_COMMIT();

    {
        size_t row = (size_t)bh * SEQ + q0 + tid;
        const float4* ps = (const float4*)&rowsum[row * 8];
        float4 s0 = ps[0], s1 = ps[1];
        sinv[tid] = 1.0f / (s0.x + s0.y + s0.z + s0.w + s1.x + s1.y + s1.z + s1.w);
    }

    float acc[2][8][4];
#pragma unroll
    for (int mt = 0; mt < 2; mt++)
#pragma unroll
        for (int nt = 0; nt < 8; nt++)
#pragma unroll
            for (int r = 0; r < 4; r++) acc[mt][nt][r] = 0.0f;

    int buf = 0;
    for (int kt = 0; kt < SEQ; kt += 32) {
        const int more = (kt + 32 < SEQ);
        if (more) { load_tile(kt + 32, buf ^ 1); CP_COMMIT(); }
        if (more) asm volatile("cp.async.wait_group 1;\n");
        else      asm volatile("cp.async.wait_group 0;\n");
        __syncthreads();

        const __half* Pd = Ps + buf * CPH_TILE;

        // attn writeback: p = e*inv (fp32), from half smem tile
#pragma unroll
        for (int r = 0; r < 4; r++) {
            int idx = tid + r * 256;
            int row = idx >> 2;
            int c   = (idx & 3) * 8;
            uint4 hv = *(const uint4*)(Pd + row * CPH_STR + c);
            const __half2* hp = (const __half2*)&hv;
            float2 f0 = __half22float2(hp[0]);
            float2 f1 = __half22float2(hp[1]);
            float2 f2 = __half22float2(hp[2]);
            float2 f3 = __half22float2(hp[3]);
            float iv = sinv[row];
            float* arow = ab + (size_t)(q0 + row) * SEQ + kt + c;
            *(float4*)arow       = make_float4(f0.x * iv, f0.y * iv, f1.x * iv, f1.y * iv);
            *(float4*)(arow + 4) = make_float4(f2.x * iv, f2.y * iv, f3.x * iv, f3.y * iv);
        }

        const unsigned pdb = pbs + (unsigned)(buf * CPH_TILE * 2);
        const unsigned vdb = vbs + (unsigned)(buf * CVH_TILE * 2);
#pragma unroll
        for (int ks = 0; ks < 2; ks++) {
            unsigned af[2][4], bf[8][2];
#pragma unroll
            for (int mt = 0; mt < 2; mt++)
                ldsm4(af[mt], pdb + (unsigned)((wid * 32 + mt * 16) * CPH_STR * 2 + ks * 32) + aL);
#pragma unroll
            for (int np = 0; np < 4; np++) {
                unsigned t4[4];
                ldsm4(t4, vdb + (unsigned)((np * 16) * CVH_STR * 2 + ks * 32) + bL);
                bf[np * 2][0] = t4[0]; bf[np * 2][1] = t4[1];
                bf[np * 2 + 1][0] = t4[2]; bf[np * 2 + 1][1] = t4[3];
            }
#pragma unroll
            for (int mt = 0; mt < 2; mt++)
#pragma unroll
                for (int nt = 0; nt < 8; nt++)
                    mmah(acc[mt][nt], af[mt], bf[nt]);
        }
        __syncthreads();
        buf ^= 1;
    }

    // epilogue: ctx = fp16(acc * inv), layout [B,S,D]
#pragma unroll
    for (int mt = 0; mt < 2; mt++) {
#pragma unroll
        for (int hf = 0; hf < 2; hf++) {
            int lrow = wid * 32 + mt * 16 + gid + hf * 8;
            int qrow = q0 + lrow;
            float invE = sinv[lrow];
            __half* crow = ctx + ((size_t)b * SEQ + qrow) * DMODEL + h * HDIM;
#pragma unroll
            for (int nt = 0; nt < 8; nt++) {
                int d = nt * 8 + t2;
                *(__half2*)(crow + d) = __floats2half2_rn(acc[mt][nt][hf * 2 + 0] * invE,
                                                          acc[mt][nt][hf * 2 + 1] * invE);
            }
        }
    }
}

// -------------------- launcher ----------------------------------------------
extern "C" void kernel_launch(void* const* d_in, const int* in_sizes, int n_in,
                              void* d_out, int out_size)
{
    const float* x  = (const float*)d_in[0];
    const float* Wq = (const float*)d_in[1];
    const float* bq = (const float*)d_in[2];
    const float* Wk = (const float*)d_in[3];
    const float* bk = (const float*)d_in[4];
    const float* Wv = (const float*)d_in[5];
    const float* bv = (const float*)d_in[6];
    const float* Wo = (const float*)d_in[7];
    const float* bo = (const float*)d_in[8];

    float* out_ptr  = (float*)d_out;                                   // [B,S,D]
    float* attn_ptr = (float*)d_out + (size_t)BATCH * SEQ * DMODEL;    // [B,H,S,S]

    __half *qp, *kp, *vtp, *cp, *xh, *wh, *ep;
    float *rs;
    cudaGetSymbolAddress((void**)&qp, g_qh);
    cudaGetSymbolAddress((void**)&kp, g_kh);
    cudaGetSymbolAddress((void**)&vtp, g_vt);
    cudaGetSymbolAddress((void**)&cp, g_ch);
    cudaGetSymbolAddress((void**)&rs, g_rowsum);
    cudaGetSymbolAddress((void**)&xh, g_xh);
    cudaGetSymbolAddress((void**)&wh, g_wh);
    cudaGetSymbolAddress((void**)&ep, g_eh);

    cudaFuncSetAttribute(proj_h_kernel,
                         cudaFuncAttributeMaxDynamicSharedMemorySize, PROJ_SMEM_BYTES);
    cudaFuncSetAttribute(scores_h_kernel,
                         cudaFuncAttributeMaxDynamicSharedMemorySize, SCORES_SMEM_BYTES);
    cudaFuncSetAttribute(ctx_h_kernel,
                         cudaFuncAttributeMaxDynamicSharedMemorySize, CTX_SMEM_BYTES);

    dim3 blk(256);

    // fp32 -> fp16 conversion of inputs
    const size_t WSZ = (size_t)DMODEL * DMODEL;
    int xn8 = (int)((size_t)MTOT * DMODEL / 8);
    int wn8 = (int)(WSZ / 8);
    tohalf_kernel<<<(xn8 + 255) / 256, blk>>>(xh, x, xn8);
    tohalf_kernel<<<(wn8 + 255) / 256, blk>>>(wh + 0 * WSZ, Wq, wn8);
    tohalf_kernel<<<(wn8 + 255) / 256, blk>>>(wh + 1 * WSZ, Wk, wn8);
    tohalf_kernel<<<(wn8 + 255) / 256, blk>>>(wh + 2 * WSZ, Wv, wn8);
    tohalf_kernel<<<(wn8 + 255) / 256, blk>>>(wh + 3 * WSZ, Wo, wn8);

    dim3 pgrid(DMODEL / 128, MTOT / 128);       // (8, 64)
    proj_h_kernel<<<pgrid, blk, PROJ_SMEM_BYTES>>>(xh, wh + 0 * WSZ, bq, nullptr, qp, 1);
    proj_h_kernel<<<pgrid, blk, PROJ_SMEM_BYTES>>>(xh, wh + 1 * WSZ, bk, nullptr, kp, 1);
    proj_h_kernel<<<pgrid, blk, PROJ_SMEM_BYTES>>>(xh, wh + 2 * WSZ, bv, nullptr, vtp, 2);

    dim3 sgrid(SEQ / 128, SEQ / 128, BATCH * HEADS);   // (8, 8, 128)
    scores_h_kernel<<<sgrid, blk, SCORES_SMEM_BYTES>>>(qp, kp, ep, rs);

    dim3 cgrid(SEQ / 256, BATCH * HEADS);              // (4, 128)
    ctx_h_kernel<<<cgrid, blk, CTX_SMEM_BYTES>>>(ep, vtp, rs, attn_ptr, cp);

    proj_h_kernel<<<pgrid, blk, PROJ_SMEM_BYTES>>>(cp, wh + 3 * WSZ, bo, out_ptr, nullptr, 0);
}

// round 14
// speedup vs baseline: 2.0354x; 1.0926x over previous
#include <cuda_runtime.h>
#include <cuda_fp16.h>
#include <math.h>

// Problem constants
#define BATCH  8
#define SEQ    1024
#define DMODEL 1024
#define HEADS  16
#define HDIM   64
#define MTOT   (BATCH * SEQ)          // 8192

// -------------------- scratch (__device__ globals; no allocs allowed) -------
__device__ __half g_qh[(size_t)BATCH * HEADS * SEQ * HDIM];   // [B,H,S,Hd]
__device__ __half g_kh[(size_t)BATCH * HEADS * SEQ * HDIM];
__device__ __half g_vt[(size_t)BATCH * HEADS * HDIM * SEQ];   // [B,H,Hd,S]
__device__ __half g_ch[(size_t)BATCH * SEQ * DMODEL];         // ctx [B,S,D]
__device__ float  g_rowsum[(size_t)BATCH * HEADS * SEQ * 8];
__device__ __half g_xh[(size_t)MTOT * DMODEL];
__device__ __half g_wh[4][(size_t)DMODEL * DMODEL];
__device__ __half g_eh[(size_t)BATCH * HEADS * SEQ * SEQ];

// -------------------- helpers ------------------------------------------------
__device__ __forceinline__ __half2 ex2h2(float t0, float t1) {
    __half2 h = __floats2half2_rn(t0, t1);
    unsigned u = *(unsigned*)&h;
    asm("ex2.approx.f16x2 %0, %0;" : "+r"(u));
    return *(__half2*)&u;
}

__device__ __forceinline__ void cpa16(void* smem, const void* gmem) {
    unsigned sa = (unsigned)__cvta_generic_to_shared(smem);
    asm volatile("cp.async.cg.shared.global [%0], [%1], 16;\n" :: "r"(sa), "l"(gmem));
}
#define CP_COMMIT() asm volatile("cp.async.commit_group;\n")

__device__ __forceinline__ unsigned s2u(const void* p) {
    unsigned a;
    asm("{ .reg .u64 t; cvta.to.shared.u64 t, %1; cvt.u32.u64 %0, t; }" : "=r"(a) : "l"(p));
    return a;
}

__device__ __forceinline__ void ldsm4(unsigned* r, unsigned addr) {
    asm volatile("ldmatrix.sync.aligned.m8n8.x4.shared.b16 {%0,%1,%2,%3}, [%4];"
                 : "=r"(r[0]), "=r"(r[1]), "=r"(r[2]), "=r"(r[3]) : "r"(addr));
}

__device__ __forceinline__ void mmah(float* c, const unsigned* a, const unsigned* b) {
    asm volatile(
        "mma.sync.aligned.m16n8k16.row.col.f32.f16.f16.f32 "
        "{%0,%1,%2,%3}, {%4,%5,%6,%7}, {%8,%9}, {%0,%1,%2,%3};\n"
        : "+f"(c[0]), "+f"(c[1]), "+f"(c[2]), "+f"(c[3])
        : "r"(a[0]), "r"(a[1]), "r"(a[2]), "r"(a[3]), "r"(b[0]), "r"(b[1]));
}

// =============================================================================
// fp32 -> fp16 conversion pre-pass (8 elems/thread)
// =============================================================================
__global__ __launch_bounds__(256)
void tohalf_kernel(__half* __restrict__ dst, const float* __restrict__ src, int n8)
{
    int i = blockIdx.x * blockDim.x + threadIdx.x;
    if (i < n8) {
        const float4* s = (const float4*)src + i * 2;
        float4 v0 = s[0], v1 = s[1];
        __half2 h[4];
        h[0] = __floats2half2_rn(v0.x, v0.y);
        h[1] = __floats2half2_rn(v0.z, v0.w);
        h[2] = __floats2half2_rn(v1.x, v1.y);
        h[3] = __floats2half2_rn(v1.z, v1.w);
        *(uint4*)(dst + (size_t)i * 8) = *(uint4*)h;
    }
}

// =============================================================================
// Projection GEMM core (fp16 mma.sync + ldmatrix), BK=64, 3-stage cp.async.
// BM=128, BN=128; 8 warps, warp tile 64x32.
// mode 0: fp32 row-major; mode 1: fp16 split-heads; mode 2: fp16 V^T.
// =============================================================================
#define PH_STR 72                       // halfs (144B rows); word stride 36 conflict-free
#define PH_TILE (128 * PH_STR)          // halfs per matrix tile
#define PH_NT (DMODEL / 64)             // 16 k-tiles
#define PROJ_SMEM_BYTES (3 * 2 * PH_TILE * 2)   // 110592

__device__ __forceinline__ void proj_body(const __half* __restrict__ A,
                                          const __half* __restrict__ W,
                                          const float* __restrict__ bias,
                                          float* __restrict__ Cf,
                                          __half* __restrict__ Ch,
                                          int mode, int m0, int n0, __half* hsm)
{
    const int tid  = threadIdx.x;
    const int wid  = tid >> 5;
    const int lane = tid & 31;
    const int gid  = lane >> 2;
    const int t2   = (lane & 3) * 2;
    const int wm = (wid >> 2) * 64;
    const int wn = (wid & 3) * 32;

    const unsigned hb = s2u(hsm);
    const int quad = lane >> 3, win = lane & 7;
    const unsigned aL = (unsigned)((win + (quad & 1) * 8) * PH_STR * 2 + (quad >> 1) * 16);
    const unsigned bL = (unsigned)((win + (quad >> 1) * 8) * PH_STR * 2 + (quad & 1) * 16);

    float acc[4][4][4];
#pragma unroll
    for (int mt = 0; mt < 4; mt++)
#pragma unroll
        for (int nt = 0; nt < 4; nt++)
#pragma unroll
            for (int r = 0; r < 4; r++) acc[mt][nt][r] = 0.0f;

    auto load_tile = [&](int kt, int s) {
        __half* As = hsm + s * 2 * PH_TILE;
        __half* Bs = As + PH_TILE;
#pragma unroll
        for (int r = 0; r < 4; r++) {
            int idx = tid + r * 256;          // 0..1023
            int row = idx >> 3;               // 0..127
            int c   = (idx & 7) * 8;          // halfs 0..56
            cpa16(&As[row * PH_STR + c], A + (size_t)(m0 + row) * DMODEL + kt + c);
            cpa16(&Bs[row * PH_STR + c], W + (size_t)(n0 + row) * DMODEL + kt + c);
        }
    };

    load_tile(0, 0); CP_COMMIT();
    load_tile(64, 1); CP_COMMIT();

    for (int t = 0; t < PH_NT; t++) {
        if (t + 2 < PH_NT) { load_tile((t + 2) * 64, (t + 2) % 3); CP_COMMIT(); }
        if (t + 2 < PH_NT)      asm volatile("cp.async.wait_group 2;\n");
        else if (t + 1 < PH_NT) asm volatile("cp.async.wait_group 1;\n");
        else                    asm volatile("cp.async.wait_group 0;\n");
        __syncthreads();

        const unsigned ab = hb + (unsigned)((t % 3) * (2 * PH_TILE * 2));
        const unsigned bb = ab + PH_TILE * 2;
#pragma unroll
        for (int ks = 0; ks < 4; ks++) {
            unsigned af[4][4], bf[4][2];
#pragma unroll
            for (int mt = 0; mt < 4; mt++)
                ldsm4(af[mt], ab + (unsigned)((wm + mt * 16) * PH_STR * 2 + ks * 32) + aL);
#pragma unroll
            for (int np = 0; np < 2; np++) {
                unsigned t4[4];
                ldsm4(t4, bb + (unsigned)((wn + np * 16) * PH_STR * 2 + ks * 32) + bL);
                bf[np * 2][0] = t4[0]; bf[np * 2][1] = t4[1];
                bf[np * 2 + 1][0] = t4[2]; bf[np * 2 + 1][1] = t4[3];
            }
#pragma unroll
            for (int mt = 0; mt < 4; mt++)
#pragma unroll
                for (int nt = 0; nt < 4; nt++)
                    mmah(acc[mt][nt], af[mt], bf[nt]);
        }
        __syncthreads();
    }

#pragma unroll
    for (int mt = 0; mt < 4; mt++) {
#pragma unroll
        for (int hf = 0; hf < 2; hf++) {
            int m  = m0 + wm + mt * 16 + gid + hf * 8;
            int bb2 = m >> 10;
            int s  = m & 1023;
#pragma unroll
            for (int nt = 0; nt < 4; nt++) {
                int n = n0 + wn + nt * 8 + t2;
                float vx = acc[mt][nt][hf * 2 + 0] + bias[n];
                float vy = acc[mt][nt][hf * 2 + 1] + bias[n + 1];
                if (mode == 0) {
                    float2 v; v.x = vx; v.y = vy;
                    *(float2*)(Cf + (size_t)m * DMODEL + n) = v;
                } else if (mode == 1) {
                    int h = n >> 6, d = n & 63;
                    size_t idx = ((((size_t)bb2 * HEADS + h) * SEQ + s) << 6) + d;
                    *(__half2*)(Ch + idx) = __floats2half2_rn(vx, vy);
                } else {
                    int h = n >> 6, d = n & 63;
                    size_t base = (((size_t)bb2 * HEADS + h) * HDIM + d) * SEQ + s;
                    Ch[base]       = __float2half_rn(vx);
                    Ch[base + SEQ] = __float2half_rn(vy);
                }
            }
        }
    }
}

// fused Q/K/V projection: blockIdx.z selects weight/bias/dst/mode
__global__ __launch_bounds__(256, 2)
void qkv_h_kernel(const __half* __restrict__ A,
                  const __half* __restrict__ W0, const __half* __restrict__ W1,
                  const __half* __restrict__ W2,
                  const float* __restrict__ b0, const float* __restrict__ b1,
                  const float* __restrict__ b2,
                  __half* __restrict__ C0, __half* __restrict__ C1,
                  __half* __restrict__ C2)
{
    extern __shared__ __half hsm[];
    const int z = blockIdx.z;
    const __half* W = (z == 0) ? W0 : (z == 1) ? W1 : W2;
    const float*  bb = (z == 0) ? b0 : (z == 1) ? b1 : b2;
    __half* Ch = (z == 0) ? C0 : (z == 1) ? C1 : C2;
    proj_body(A, W, bb, nullptr, Ch, (z == 2) ? 2 : 1,
              blockIdx.y * 128, blockIdx.x * 128, hsm);
}

// final O projection (fp32 output)
__global__ __launch_bounds__(256, 2)
void proj_o_kernel(const __half* __restrict__ A, const __half* __restrict__ W,
                   const float* __restrict__ bias, float* __restrict__ Cf)
{
    extern __shared__ __half hsm[];
    proj_body(A, W, bias, Cf, nullptr, 0, blockIdx.y * 128, blockIdx.x * 128, hsm);
}

// =============================================================================
// Scores (fp16 mma.sync + ldmatrix): e = fp16(2^(s*0.125*log2e)) + rowsums.
// Tiles 128x128, K=64; per (b,h); one-shot smem.
// =============================================================================
#define SH_STR 72
#define SH_TILE (128 * SH_STR)
#define SCORES_SMEM_BYTES (2 * SH_TILE * 2)   // 36864
#define SCALE_LOG2E 0.18033688f

__global__ __launch_bounds__(256, 2)
void scores_h_kernel(const __half* __restrict__ q, const __half* __restrict__ k,
                     __half* __restrict__ eh, float* __restrict__ rowsum)
{
    extern __shared__ __half ssm[];
    __half* Qs = ssm;
    __half* Ks = ssm + SH_TILE;
    __shared__ float sexp[128];

    const int tid  = threadIdx.x;
    const int wid  = tid >> 5;
    const int lane = tid & 31;
    const int gid  = lane >> 2;
    const int t2   = (lane & 3) * 2;
    const int bh = blockIdx.z;
    const int q0 = blockIdx.y * 128;
    const int k0 = blockIdx.x * 128;
    const int kb = blockIdx.x;
    const int wm = (wid >> 2) * 64;
    const int wn = (wid & 3) * 32;

    const unsigned qbs = s2u(ssm);
    const unsigned kbs = qbs + SH_TILE * 2;
    const int quad = lane >> 3, win = lane & 7;
    const unsigned aL = (unsigned)((win + (quad & 1) * 8) * SH_STR * 2 + (quad >> 1) * 16);
    const unsigned bL = (unsigned)((win + (quad >> 1) * 8) * SH_STR * 2 + (quad & 1) * 16);

    const __half* qb = q + (size_t)bh * SEQ * HDIM;
    const __half* kp = k + (size_t)bh * SEQ * HDIM;

#pragma unroll
    for (int r = 0; r < 4; r++) {
        int idx = tid + r * 256;
        int row = idx >> 3;
        int c   = (idx & 7) * 8;
        cpa16(&Qs[row * SH_STR + c], qb + (size_t)(q0 + row) * HDIM + c);
        cpa16(&Ks[row * SH_STR + c], kp + (size_t)(k0 + row) * HDIM + c);
    }
    CP_COMMIT();
    if (tid < 128) sexp[tid] = 0.0f;
    asm volatile("cp.async.wait_group 0;\n");
    __syncthreads();

    float acc[4][4][4];
#pragma unroll
    for (int mt = 0; mt < 4; mt++)
#pragma unroll
        for (int nt = 0; nt < 4; nt++)
#pragma unroll
            for (int r = 0; r < 4; r++) acc[mt][nt][r] = 0.0f;

#pragma unroll
    for (int ks = 0; ks < 4; ks++) {
        unsigned af[4][4], bf[4][2];
#pragma unroll
        for (int mt = 0; mt < 4; mt++)
            ldsm4(af[mt], qbs + (unsigned)((wm + mt * 16) * SH_STR * 2 + ks * 32) + aL);
#pragma unroll
        for (int np = 0; np < 2; np++) {
            unsigned t4[4];
            ldsm4(t4, kbs + (unsigned)((wn + np * 16) * SH_STR * 2 + ks * 32) + bL);
            bf[np * 2][0] = t4[0]; bf[np * 2][1] = t4[1];
            bf[np * 2 + 1][0] = t4[2]; bf[np * 2 + 1][1] = t4[3];
        }
#pragma unroll
        for (int mt = 0; mt < 4; mt++)
#pragma unroll
            for (int nt = 0; nt < 4; nt++)
                mmah(acc[mt][nt], af[mt], bf[nt]);
    }

    __half* eb = eh + (size_t)bh * SEQ * SEQ;
#pragma unroll
    for (int mt = 0; mt < 4; mt++) {
#pragma unroll
        for (int hf = 0; hf < 2; hf++) {
            int lr = wm + mt * 16 + gid + hf * 8;
            int sq = q0 + lr;
            float lsum = 0.0f;
#pragma unroll
            for (int nt = 0; nt < 4; nt++) {
                int sk = k0 + wn + nt * 8 + t2;
                __half2 e2 = ex2h2(acc[mt][nt][hf * 2 + 0] * SCALE_LOG2E,
                                   acc[mt][nt][hf * 2 + 1] * SCALE_LOG2E);
                *(__half2*)(eb + (size_t)sq * SEQ + sk) = e2;
                float2 ef = __half22float2(e2);
                lsum += ef.x + ef.y;
            }
            lsum += __shfl_xor_sync(0xffffffffu, lsum, 1);
            lsum += __shfl_xor_sync(0xffffffffu, lsum, 2);
            if ((lane & 3) == 0) atomicAdd(&sexp[lr], lsum);
        }
    }
    __syncthreads();
    if (tid < 128)
        rowsum[((size_t)bh * SEQ + q0 + tid) * 8 + kb] = sexp[tid];
}

// =============================================================================
// Context (fp16 mma.sync + ldmatrix): P = e direct, B = V^T tiles. Writes
// final attn (fp32, normalized) and ctx (fp16, [B,S,D], output-normalized).
// BM=256, N=64, BK=32; 8 warps; 2-stage cp.async.
// =============================================================================
#define CPH_STR 40
#define CVH_STR 40
#define CPH_TILE (256 * CPH_STR)
#define CVH_TILE (64 * CVH_STR)
#define CTX_SMEM_BYTES (2 * (CPH_TILE + CVH_TILE) * 2)   // 51200

__global__ __launch_bounds__(256, 2)
void ctx_h_kernel(const __half* __restrict__ eh, const __half* __restrict__ vt,
                  const float* __restrict__ rowsum, float* __restrict__ attn,
                  __half* __restrict__ ctx)
{
    extern __shared__ __half csm[];
    __half* Ps = csm;
    __half* Vs = csm + 2 * CPH_TILE;
    __shared__ float sinv[256];

    const int tid  = threadIdx.x;
    const int wid  = tid >> 5;
    const int lane = tid & 31;
    const int gid  = lane >> 2;
    const int t2   = (lane & 3) * 2;
    const int bh = blockIdx.y;
    const int q0 = blockIdx.x * 256;
    const int b = bh >> 4, h = bh & 15;

    const unsigned pbs = s2u(csm);
    const unsigned vbs = pbs + 2 * CPH_TILE * 2;
    const int quad = lane >> 3, win = lane & 7;
    const unsigned aL = (unsigned)((win + (quad & 1) * 8) * CPH_STR * 2 + (quad >> 1) * 16);
    const unsigned bL = (unsigned)((win + (quad >> 1) * 8) * CVH_STR * 2 + (quad & 1) * 16);

    const __half* pb  = eh + (size_t)bh * SEQ * SEQ;
    const __half* vtb = vt + (size_t)bh * HDIM * SEQ;
    float* ab = attn + (size_t)bh * SEQ * SEQ;

    auto load_tile = [&](int kt, int s) {
        __half* Pd = Ps + s * CPH_TILE;
        __half* Vd = Vs + s * CVH_TILE;
#pragma unroll
        for (int r = 0; r < 4; r++) {
            int idx = tid + r * 256;
            int row = idx >> 2;
            int c   = (idx & 3) * 8;
            cpa16(&Pd[row * CPH_STR + c], pb + (size_t)(q0 + row) * SEQ + kt + c);
        }
        {
            int row = tid >> 2;
            int c   = (tid & 3) * 8;
            cpa16(&Vd[row * CVH_STR + c], vtb + (size_t)row * SEQ + kt + c);
        }
    };

    load_tile(0, 0); CP_COMMIT();

    {
        size_t row = (size_t)bh * SEQ + q0 + tid;
        const float4* ps = (const float4*)&rowsum[row * 8];
        float4 s0 = ps[0], s1 = ps[1];
        sinv[tid] = 1.0f / (s0.x + s0.y + s0.z + s0.w + s1.x + s1.y + s1.z + s1.w);
    }

    float acc[2][8][4];
#pragma unroll
    for (int mt = 0; mt < 2; mt++)
#pragma unroll
        for (int nt = 0; nt < 8; nt++)
#pragma unroll
            for (int r = 0; r < 4; r++) acc[mt][nt][r] = 0.0f;

    int buf = 0;
    for (int kt = 0; kt < SEQ; kt += 32) {
        const int more = (kt + 32 < SEQ);
        if (more) { load_tile(kt + 32, buf ^ 1); CP_COMMIT(); }
        if (more) asm volatile("cp.async.wait_group 1;\n");
        else      asm volatile("cp.async.wait_group 0;\n");
        __syncthreads();

        const __half* Pd = Ps + buf * CPH_TILE;

#pragma unroll
        for (int r = 0; r < 4; r++) {
            int idx = tid + r * 256;
            int row = idx >> 2;
            int c   = (idx & 3) * 8;
            uint4 hv = *(const uint4*)(Pd + row * CPH_STR + c);
            const __half2* hp = (const __half2*)&hv;
            float2 f0 = __half22float2(hp[0]);
            float2 f1 = __half22float2(hp[1]);
            float2 f2 = __half22float2(hp[2]);
            float2 f3 = __half22float2(hp[3]);
            float iv = sinv[row];
            float* arow = ab + (size_t)(q0 + row) * SEQ + kt + c;
            *(float4*)arow       = make_float4(f0.x * iv, f0.y * iv, f1.x * iv, f1.y * iv);
            *(float4*)(arow + 4) = make_float4(f2.x * iv, f2.y * iv, f3.x * iv, f3.y * iv);
        }

        const unsigned pdb = pbs + (unsigned)(buf * CPH_TILE * 2);
        const unsigned vdb = vbs + (unsigned)(buf * CVH_TILE * 2);
#pragma unroll
        for (int ks = 0; ks < 2; ks++) {
            unsigned af[2][4], bf[8][2];
#pragma unroll
            for (int mt = 0; mt < 2; mt++)
                ldsm4(af[mt], pdb + (unsigned)((wid * 32 + mt * 16) * CPH_STR * 2 + ks * 32) + aL);
#pragma unroll
            for (int np = 0; np < 4; np++) {
                unsigned t4[4];
                ldsm4(t4, vdb + (unsigned)((np * 16) * CVH_STR * 2 + ks * 32) + bL);
                bf[np * 2][0] = t4[0]; bf[np * 2][1] = t4[1];
                bf[np * 2 + 1][0] = t4[2]; bf[np * 2 + 1][1] = t4[3];
            }
#pragma unroll
            for (int mt = 0; mt < 2; mt++)
#pragma unroll
                for (int nt = 0; nt < 8; nt++)
                    mmah(acc[mt][nt], af[mt], bf[nt]);
        }
        __syncthreads();
        buf ^= 1;
    }

#pragma unroll
    for (int mt = 0; mt < 2; mt++) {
#pragma unroll
        for (int hf = 0; hf < 2; hf++) {
            int lrow = wid * 32 + mt * 16 + gid + hf * 8;
            int qrow = q0 + lrow;
            float invE = sinv[lrow];
            __half* crow = ctx + ((size_t)b * SEQ + qrow) * DMODEL + h * HDIM;
#pragma unroll
            for (int nt = 0; nt < 8; nt++) {
                int d = nt * 8 + t2;
                *(__half2*)(crow + d) = __floats2half2_rn(acc[mt][nt][hf * 2 + 0] * invE,
                                                          acc[mt][nt][hf * 2 + 1] * invE);
            }
        }
    }
}

// -------------------- launcher ----------------------------------------------
extern "C" void kernel_launch(void* const* d_in, const int* in_sizes, int n_in,
                              void* d_out, int out_size)
{
    const float* x  = (const float*)d_in[0];
    const float* Wq = (const float*)d_in[1];
    const float* bq = (const float*)d_in[2];
    const float* Wk = (const float*)d_in[3];
    const float* bk = (const float*)d_in[4];
    const float* Wv = (const float*)d_in[5];
    const float* bv = (const float*)d_in[6];
    const float* Wo = (const float*)d_in[7];
    const float* bo = (const float*)d_in[8];

    float* out_ptr  = (float*)d_out;                                   // [B,S,D]
    float* attn_ptr = (float*)d_out + (size_t)BATCH * SEQ * DMODEL;    // [B,H,S,S]

    __half *qp, *kp, *vtp, *cp, *xh, *wh, *ep;
    float *rs;
    cudaGetSymbolAddress((void**)&qp, g_qh);
    cudaGetSymbolAddress((void**)&kp, g_kh);
    cudaGetSymbolAddress((void**)&vtp, g_vt);
    cudaGetSymbolAddress((void**)&cp, g_ch);
    cudaGetSymbolAddress((void**)&rs, g_rowsum);
    cudaGetSymbolAddress((void**)&xh, g_xh);
    cudaGetSymbolAddress((void**)&wh, g_wh);
    cudaGetSymbolAddress((void**)&ep, g_eh);

    cudaFuncSetAttribute(qkv_h_kernel,
                         cudaFuncAttributeMaxDynamicSharedMemorySize, PROJ_SMEM_BYTES);
    cudaFuncSetAttribute(proj_o_kernel,
                         cudaFuncAttributeMaxDynamicSharedMemorySize, PROJ_SMEM_BYTES);
    cudaFuncSetAttribute(scores_h_kernel,
                         cudaFuncAttributeMaxDynamicSharedMemorySize, SCORES_SMEM_BYTES);
    cudaFuncSetAttribute(ctx_h_kernel,
                         cudaFuncAttributeMaxDynamicSharedMemorySize, CTX_SMEM_BYTES);

    dim3 blk(256);

    // fp32 -> fp16 conversion of inputs
    const size_t WSZ = (size_t)DMODEL * DMODEL;
    int xn8 = (int)((size_t)MTOT * DMODEL / 8);
    int wn8 = (int)(WSZ / 8);
    tohalf_kernel<<<(xn8 + 255) / 256, blk>>>(xh, x, xn8);
    tohalf_kernel<<<(wn8 + 255) / 256, blk>>>(wh + 0 * WSZ, Wq, wn8);
    tohalf_kernel<<<(wn8 + 255) / 256, blk>>>(wh + 1 * WSZ, Wk, wn8);
    tohalf_kernel<<<(wn8 + 255) / 256, blk>>>(wh + 2 * WSZ, Wv, wn8);
    tohalf_kernel<<<(wn8 + 255) / 256, blk>>>(wh + 3 * WSZ, Wo, wn8);

    // fused Q/K/V projection: grid.z = 3
    dim3 qkvgrid(DMODEL / 128, MTOT / 128, 3);  // (8, 64, 3)
    qkv_h_kernel<<<qkvgrid, blk, PROJ_SMEM_BYTES>>>(
        xh, wh + 0 * WSZ, wh + 1 * WSZ, wh + 2 * WSZ, bq, bk, bv, qp, kp, vtp);

    dim3 sgrid(SEQ / 128, SEQ / 128, BATCH * HEADS);   // (8, 8, 128)
    scores_h_kernel<<<sgrid, blk, SCORES_SMEM_BYTES>>>(qp, kp, ep, rs);

    dim3 cgrid(SEQ / 256, BATCH * HEADS);              // (4, 128)
    ctx_h_kernel<<<cgrid, blk, CTX_SMEM_BYTES>>>(ep, vtp, rs, attn_ptr, cp);

    dim3 ogrid(DMODEL / 128, MTOT / 128);              // (8, 64)
    proj_o_kernel<<<ogrid, blk, PROJ_SMEM_BYTES>>>(cp, wh + 3 * WSZ, bo, out_ptr);
}

// round 17
// speedup vs baseline: 2.1156x; 1.0394x over previous
#include <cuda_runtime.h>
#include <cuda_fp16.h>
#include <math.h>

// Problem constants
#define BATCH  8
#define SEQ    1024
#define DMODEL 1024
#define HEADS  16
#define HDIM   64
#define MTOT   (BATCH * SEQ)          // 8192

// -------------------- scratch (__device__ globals; no allocs allowed) -------
__device__ __half g_qh[(size_t)BATCH * HEADS * SEQ * HDIM];   // [B,H,S,Hd]
__device__ __half g_kh[(size_t)BATCH * HEADS * SEQ * HDIM];
__device__ __half g_vt[(size_t)BATCH * HEADS * HDIM * SEQ];   // [B,H,Hd,S]
__device__ __half g_ch[(size_t)BATCH * SEQ * DMODEL];         // ctx [B,S,D]
__device__ float  g_rowsum[(size_t)BATCH * HEADS * SEQ * 8];
__device__ __half g_xh[(size_t)MTOT * DMODEL];
__device__ __half g_wh[4][(size_t)DMODEL * DMODEL];
__device__ __half g_eh[(size_t)BATCH * HEADS * SEQ * SEQ];

// -------------------- helpers ------------------------------------------------
__device__ __forceinline__ __half2 ex2h2(float t0, float t1) {
    __half2 h = __floats2half2_rn(t0, t1);
    unsigned u = *(unsigned*)&h;
    asm("ex2.approx.f16x2 %0, %0;" : "+r"(u));
    return *(__half2*)&u;
}

__device__ __forceinline__ void cpa16(void* smem, const void* gmem) {
    unsigned sa = (unsigned)__cvta_generic_to_shared(smem);
    asm volatile("cp.async.cg.shared.global [%0], [%1], 16;\n" :: "r"(sa), "l"(gmem));
}
#define CP_COMMIT() asm volatile("cp.async.commit_group;\n")

__device__ __forceinline__ unsigned s2u(const void* p) {
    unsigned a;
    asm("{ .reg .u64 t; cvta.to.shared.u64 t, %1; cvt.u32.u64 %0, t; }" : "=r"(a) : "l"(p));
    return a;
}

__device__ __forceinline__ void ldsm4(unsigned* r, unsigned addr) {
    asm volatile("ldmatrix.sync.aligned.m8n8.x4.shared.b16 {%0,%1,%2,%3}, [%4];"
                 : "=r"(r[0]), "=r"(r[1]), "=r"(r[2]), "=r"(r[3]) : "r"(addr));
}

__device__ __forceinline__ void mmah(float* c, const unsigned* a, const unsigned* b) {
    asm volatile(
        "mma.sync.aligned.m16n8k16.row.col.f32.f16.f16.f32 "
        "{%0,%1,%2,%3}, {%4,%5,%6,%7}, {%8,%9}, {%0,%1,%2,%3};\n"
        : "+f"(c[0]), "+f"(c[1]), "+f"(c[2]), "+f"(c[3])
        : "r"(a[0]), "r"(a[1]), "r"(a[2]), "r"(a[3]), "r"(b[0]), "r"(b[1]));
}

// =============================================================================
// Merged fp32 -> fp16 conversion: x (1M n8-chunks) + 4 weights (128K each)
// =============================================================================
#define XN8 ((size_t)MTOT * DMODEL / 8)          // 1048576
#define WN8 ((size_t)DMODEL * DMODEL / 8)        // 131072

__global__ __launch_bounds__(256)
void tohalf_all_kernel(const float* __restrict__ x,
                       const float* __restrict__ w0, const float* __restrict__ w1,
                       const float* __restrict__ w2, const float* __restrict__ w3,
                       __half* __restrict__ xh, __half* __restrict__ wh)
{
    size_t i = (size_t)blockIdx.x * blockDim.x + threadIdx.x;
    const float* src;
    __half* dst;
    size_t off;
    if (i < XN8) {
        src = x; dst = xh; off = i;
    } else {
        size_t j = i - XN8;
        int w = (int)(j >> 17);           // / 131072
        off = j & (WN8 - 1);
        src = (w == 0) ? w0 : (w == 1) ? w1 : (w == 2) ? w2 : w3;
        dst = wh + (size_t)w * DMODEL * DMODEL;
    }
    const float4* s = (const float4*)src + off * 2;
    float4 v0 = s[0], v1 = s[1];
    __half2 h[4];
    h[0] = __floats2half2_rn(v0.x, v0.y);
    h[1] = __floats2half2_rn(v0.z, v0.w);
    h[2] = __floats2half2_rn(v1.x, v1.y);
    h[3] = __floats2half2_rn(v1.z, v1.w);
    *(uint4*)(dst + off * 8) = *(uint4*)h;
}

// =============================================================================
// Projection GEMM core (fp16 mma.sync + ldmatrix), BK=64, 3-stage cp.async.
// BM=128, BN=128; 8 warps, warp tile 64x32.
// mode 0: fp32 row-major; mode 1: fp16 split-heads; mode 2: fp16 V^T.
// =============================================================================
#define PH_STR 72
#define PH_TILE (128 * PH_STR)
#define PH_NT (DMODEL / 64)             // 16 k-tiles
#define PROJ_SMEM_BYTES (3 * 2 * PH_TILE * 2)   // 110592

__device__ __forceinline__ void proj_body(const __half* __restrict__ A,
                                          const __half* __restrict__ W,
                                          const float* __restrict__ bias,
                                          float* __restrict__ Cf,
                                          __half* __restrict__ Ch,
                                          int mode, int m0, int n0, __half* hsm)
{
    const int tid  = threadIdx.x;
    const int wid  = tid >> 5;
    const int lane = tid & 31;
    const int gid  = lane >> 2;
    const int t2   = (lane & 3) * 2;
    const int wm = (wid >> 2) * 64;
    const int wn = (wid & 3) * 32;

    const unsigned hb = s2u(hsm);
    const int quad = lane >> 3, win = lane & 7;
    const unsigned aL = (unsigned)((win + (quad & 1) * 8) * PH_STR * 2 + (quad >> 1) * 16);
    const unsigned bL = (unsigned)((win + (quad >> 1) * 8) * PH_STR * 2 + (quad & 1) * 16);

    float acc[4][4][4];
#pragma unroll
    for (int mt = 0; mt < 4; mt++)
#pragma unroll
        for (int nt = 0; nt < 4; nt++)
#pragma unroll
            for (int r = 0; r < 4; r++) acc[mt][nt][r] = 0.0f;

    auto load_tile = [&](int kt, int s) {
        __half* As = hsm + s * 2 * PH_TILE;
        __half* Bs = As + PH_TILE;
#pragma unroll
        for (int r = 0; r < 4; r++) {
            int idx = tid + r * 256;
            int row = idx >> 3;
            int c   = (idx & 7) * 8;
            cpa16(&As[row * PH_STR + c], A + (size_t)(m0 + row) * DMODEL + kt + c);
            cpa16(&Bs[row * PH_STR + c], W + (size_t)(n0 + row) * DMODEL + kt + c);
        }
    };

    load_tile(0, 0); CP_COMMIT();
    load_tile(64, 1); CP_COMMIT();

    for (int t = 0; t < PH_NT; t++) {
        if (t + 2 < PH_NT) { load_tile((t + 2) * 64, (t + 2) % 3); CP_COMMIT(); }
        if (t + 2 < PH_NT)      asm volatile("cp.async.wait_group 2;\n");
        else if (t + 1 < PH_NT) asm volatile("cp.async.wait_group 1;\n");
        else                    asm volatile("cp.async.wait_group 0;\n");
        __syncthreads();

        const unsigned ab = hb + (unsigned)((t % 3) * (2 * PH_TILE * 2));
        const unsigned bb = ab + PH_TILE * 2;
#pragma unroll
        for (int ks = 0; ks < 4; ks++) {
            unsigned af[4][4], bf[4][2];
#pragma unroll
            for (int mt = 0; mt < 4; mt++)
                ldsm4(af[mt], ab + (unsigned)((wm + mt * 16) * PH_STR * 2 + ks * 32) + aL);
#pragma unroll
            for (int np = 0; np < 2; np++) {
                unsigned t4[4];
                ldsm4(t4, bb + (unsigned)((wn + np * 16) * PH_STR * 2 + ks * 32) + bL);
                bf[np * 2][0] = t4[0]; bf[np * 2][1] = t4[1];
                bf[np * 2 + 1][0] = t4[2]; bf[np * 2 + 1][1] = t4[3];
            }
#pragma unroll
            for (int mt = 0; mt < 4; mt++)
#pragma unroll
                for (int nt = 0; nt < 4; nt++)
                    mmah(acc[mt][nt], af[mt], bf[nt]);
        }
        __syncthreads();
    }

#pragma unroll
    for (int mt = 0; mt < 4; mt++) {
#pragma unroll
        for (int hf = 0; hf < 2; hf++) {
            int m  = m0 + wm + mt * 16 + gid + hf * 8;
            int bb2 = m >> 10;
            int s  = m & 1023;
#pragma unroll
            for (int nt = 0; nt < 4; nt++) {
                int n = n0 + wn + nt * 8 + t2;
                float vx = acc[mt][nt][hf * 2 + 0] + bias[n];
                float vy = acc[mt][nt][hf * 2 + 1] + bias[n + 1];
                if (mode == 0) {
                    float2 v; v.x = vx; v.y = vy;
                    *(float2*)(Cf + (size_t)m * DMODEL + n) = v;
                } else if (mode == 1) {
                    int h = n >> 6, d = n & 63;
                    size_t idx = ((((size_t)bb2 * HEADS + h) * SEQ + s) << 6) + d;
                    *(__half2*)(Ch + idx) = __floats2half2_rn(vx, vy);
                } else {
                    int h = n >> 6, d = n & 63;
                    size_t base = (((size_t)bb2 * HEADS + h) * HDIM + d) * SEQ + s;
                    Ch[base]       = __float2half_rn(vx);
                    Ch[base + SEQ] = __float2half_rn(vy);
                }
            }
        }
    }
}

__global__ __launch_bounds__(256, 2)
void qkv_h_kernel(const __half* __restrict__ A,
                  const __half* __restrict__ W0, const __half* __restrict__ W1,
                  const __half* __restrict__ W2,
                  const float* __restrict__ b0, const float* __restrict__ b1,
                  const float* __restrict__ b2,
                  __half* __restrict__ C0, __half* __restrict__ C1,
                  __half* __restrict__ C2)
{
    extern __shared__ __half hsm[];
    const int z = blockIdx.z;
    const __half* W = (z == 0) ? W0 : (z == 1) ? W1 : W2;
    const float*  bb = (z == 0) ? b0 : (z == 1) ? b1 : b2;
    __half* Ch = (z == 0) ? C0 : (z == 1) ? C1 : C2;
    proj_body(A, W, bb, nullptr, Ch, (z == 2) ? 2 : 1,
              blockIdx.y * 128, blockIdx.x * 128, hsm);
}

__global__ __launch_bounds__(256, 2)
void proj_o_kernel(const __half* __restrict__ A, const __half* __restrict__ W,
                   const float* __restrict__ bias, float* __restrict__ Cf)
{
    extern __shared__ __half hsm[];
    proj_body(A, W, bias, Cf, nullptr, 0, blockIdx.y * 128, blockIdx.x * 128, hsm);
}

// =============================================================================
// Scores (fp16 mma.sync + ldmatrix): e = fp16(2^(s*0.125*log2e)) + rowsums.
// Tiles 128x128, K=64; per (b,h); one-shot smem.
// =============================================================================
#define SH_STR 72
#define SH_TILE (128 * SH_STR)
#define SCORES_SMEM_BYTES (2 * SH_TILE * 2)   // 36864
#define SCALE_LOG2E 0.18033688f

__global__ __launch_bounds__(256, 2)
void scores_h_kernel(const __half* __restrict__ q, const __half* __restrict__ k,
                     __half* __restrict__ eh, float* __restrict__ rowsum)
{
    extern __shared__ __half ssm[];
    __half* Qs = ssm;
    __half* Ks = ssm + SH_TILE;
    __shared__ float sexp[128];

    const int tid  = threadIdx.x;
    const int wid  = tid >> 5;
    const int lane = tid & 31;
    const int gid  = lane >> 2;
    const int t2   = (lane & 3) * 2;
    const int bh = blockIdx.z;
    const int q0 = blockIdx.y * 128;
    const int k0 = blockIdx.x * 128;
    const int kb = blockIdx.x;
    const int wm = (wid >> 2) * 64;
    const int wn = (wid & 3) * 32;

    const unsigned qbs = s2u(ssm);
    const unsigned kbs = qbs + SH_TILE * 2;
    const int quad = lane >> 3, win = lane & 7;
    const unsigned aL = (unsigned)((win + (quad & 1) * 8) * SH_STR * 2 + (quad >> 1) * 16);
    const unsigned bL = (unsigned)((win + (quad >> 1) * 8) * SH_STR * 2 + (quad & 1) * 16);

    const __half* qb = q + (size_t)bh * SEQ * HDIM;
    const __half* kp = k + (size_t)bh * SEQ * HDIM;

#pragma unroll
    for (int r = 0; r < 4; r++) {
        int idx = tid + r * 256;
        int row = idx >> 3;
        int c   = (idx & 7) * 8;
        cpa16(&Qs[row * SH_STR + c], qb + (size_t)(q0 + row) * HDIM + c);
        cpa16(&Ks[row * SH_STR + c], kp + (size_t)(k0 + row) * HDIM + c);
    }
    CP_COMMIT();
    if (tid < 128) sexp[tid] = 0.0f;
    asm volatile("cp.async.wait_group 0;\n");
    __syncthreads();

    float acc[4][4][4];
#pragma unroll
    for (int mt = 0; mt < 4; mt++)
#pragma unroll
        for (int nt = 0; nt < 4; nt++)
#pragma unroll
            for (int r = 0; r < 4; r++) acc[mt][nt][r] = 0.0f;

#pragma unroll
    for (int ks = 0; ks < 4; ks++) {
        unsigned af[4][4], bf[4][2];
#pragma unroll
        for (int mt = 0; mt < 4; mt++)
            ldsm4(af[mt], qbs + (unsigned)((wm + mt * 16) * SH_STR * 2 + ks * 32) + aL);
#pragma unroll
        for (int np = 0; np < 2; np++) {
            unsigned t4[4];
            ldsm4(t4, kbs + (unsigned)((wn + np * 16) * SH_STR * 2 + ks * 32) + bL);
            bf[np * 2][0] = t4[0]; bf[np * 2][1] = t4[1];
            bf[np * 2 + 1][0] = t4[2]; bf[np * 2 + 1][1] = t4[3];
        }
#pragma unroll
        for (int mt = 0; mt < 4; mt++)
#pragma unroll
            for (int nt = 0; nt < 4; nt++)
                mmah(acc[mt][nt], af[mt], bf[nt]);
    }

    __half* eb = eh + (size_t)bh * SEQ * SEQ;
#pragma unroll
    for (int mt = 0; mt < 4; mt++) {
#pragma unroll
        for (int hf = 0; hf < 2; hf++) {
            int lr = wm + mt * 16 + gid + hf * 8;
            int sq = q0 + lr;
            float lsum = 0.0f;
#pragma unroll
            for (int nt = 0; nt < 4; nt++) {
                int sk = k0 + wn + nt * 8 + t2;
                __half2 e2 = ex2h2(acc[mt][nt][hf * 2 + 0] * SCALE_LOG2E,
                                   acc[mt][nt][hf * 2 + 1] * SCALE_LOG2E);
                *(__half2*)(eb + (size_t)sq * SEQ + sk) = e2;
                float2 ef = __half22float2(e2);
                lsum += ef.x + ef.y;
            }
            lsum += __shfl_xor_sync(0xffffffffu, lsum, 1);
            lsum += __shfl_xor_sync(0xffffffffu, lsum, 2);
            if ((lane & 3) == 0) atomicAdd(&sexp[lr], lsum);
        }
    }
    __syncthreads();
    if (tid < 128)
        rowsum[((size_t)bh * SEQ + q0 + tid) * 8 + kb] = sexp[tid];
}

// =============================================================================
// Context (fp16 mma.sync + ldmatrix), BK=64: P = e direct, B = V^T tiles.
// Writes final attn (fp32, normalized) and ctx (fp16, output-normalized).
// BM=256, N=64; 8 warps; 2-stage cp.async.
// =============================================================================
#define CPH_STR 72
#define CVH_STR 72
#define CPH_TILE (256 * CPH_STR)        // halfs per stage
#define CVH_TILE (64 * CVH_STR)
#define CTX_SMEM_BYTES (2 * (CPH_TILE + CVH_TILE) * 2)   // 92160

__global__ __launch_bounds__(256, 2)
void ctx_h_kernel(const __half* __restrict__ eh, const __half* __restrict__ vt,
                  const float* __restrict__ rowsum, float* __restrict__ attn,
                  __half* __restrict__ ctx)
{
    extern __shared__ __half csm[];
    __half* Ps = csm;
    __half* Vs = csm + 2 * CPH_TILE;
    __shared__ float sinv[256];

    const int tid  = threadIdx.x;
    const int wid  = tid >> 5;
    const int lane = tid & 31;
    const int gid  = lane >> 2;
    const int t2   = (lane & 3) * 2;
    const int bh = blockIdx.y;
    const int q0 = blockIdx.x * 256;
    const int b = bh >> 4, h = bh & 15;

    const unsigned pbs = s2u(csm);
    const unsigned vbs = pbs + 2 * CPH_TILE * 2;
    const int quad = lane >> 3, win = lane & 7;
    const unsigned aL = (unsigned)((win + (quad & 1) * 8) * CPH_STR * 2 + (quad >> 1) * 16);
    const unsigned bL = (unsigned)((win + (quad >> 1) * 8) * CVH_STR * 2 + (quad & 1) * 16);

    const __half* pb  = eh + (size_t)bh * SEQ * SEQ;
    const __half* vtb = vt + (size_t)bh * HDIM * SEQ;
    float* ab = attn + (size_t)bh * SEQ * SEQ;

    auto load_tile = [&](int kt, int s) {
        __half* Pd = Ps + s * CPH_TILE;
        __half* Vd = Vs + s * CVH_TILE;
#pragma unroll
        for (int r = 0; r < 8; r++) {
            int idx = tid + r * 256;        // 0..2047
            int row = idx >> 3;             // 0..255
            int c   = (idx & 7) * 8;        // halfs 0..56
            cpa16(&Pd[row * CPH_STR + c], pb + (size_t)(q0 + row) * SEQ + kt + c);
        }
#pragma unroll
        for (int r = 0; r < 2; r++) {
            int idx = tid + r * 256;        // 0..511
            int row = idx >> 3;             // 0..63
            int c   = (idx & 7) * 8;
            cpa16(&Vd[row * CVH_STR + c], vtb + (size_t)row * SEQ + kt + c);
        }
    };

    load_tile(0, 0); CP_COMMIT();

    {
        size_t row = (size_t)bh * SEQ + q0 + tid;
        const float4* ps = (const float4*)&rowsum[row * 8];
        float4 s0 = ps[0], s1 = ps[1];
        sinv[tid] = 1.0f / (s0.x + s0.y + s0.z + s0.w + s1.x + s1.y + s1.z + s1.w);
    }

    float acc[2][8][4];
#pragma unroll
    for (int mt = 0; mt < 2; mt++)
#pragma unroll
        for (int nt = 0; nt < 8; nt++)
#pragma unroll
            for (int r = 0; r < 4; r++) acc[mt][nt][r] = 0.0f;

    int buf = 0;
    for (int kt = 0; kt < SEQ; kt += 64) {
        const int more = (kt + 64 < SEQ);
        if (more) { load_tile(kt + 64, buf ^ 1); CP_COMMIT(); }
        if (more) asm volatile("cp.async.wait_group 1;\n");
        else      asm volatile("cp.async.wait_group 0;\n");
        __syncthreads();

        const __half* Pd = Ps + buf * CPH_TILE;

        // attn writeback: p = e*inv (fp32), from half smem tile
#pragma unroll
        for (int r = 0; r < 8; r++) {
            int idx = tid + r * 256;
            int row = idx >> 3;
            int c   = (idx & 7) * 8;
            uint4 hv = *(const uint4*)(Pd + row * CPH_STR + c);
            const __half2* hp = (const __half2*)&hv;
            float2 f0 = __half22float2(hp[0]);
            float2 f1 = __half22float2(hp[1]);
            float2 f2 = __half22float2(hp[2]);
            float2 f3 = __half22float2(hp[3]);
            float iv = sinv[row];
            float* arow = ab + (size_t)(q0 + row) * SEQ + kt + c;
            *(float4*)arow       = make_float4(f0.x * iv, f0.y * iv, f1.x * iv, f1.y * iv);
            *(float4*)(arow + 4) = make_float4(f2.x * iv, f2.y * iv, f3.x * iv, f3.y * iv);
        }

        const unsigned pdb = pbs + (unsigned)(buf * CPH_TILE * 2);
        const unsigned vdb = vbs + (unsigned)(buf * CVH_TILE * 2);
#pragma unroll
        for (int ks = 0; ks < 4; ks++) {
            unsigned af[2][4], bf[8][2];
#pragma unroll
            for (int mt = 0; mt < 2; mt++)
                ldsm4(af[mt], pdb + (unsigned)((wid * 32 + mt * 16) * CPH_STR * 2 + ks * 32) + aL);
#pragma unroll
            for (int np = 0; np < 4; np++) {
                unsigned t4[4];
                ldsm4(t4, vdb + (unsigned)((np * 16) * CVH_STR * 2 + ks * 32) + bL);
                bf[np * 2][0] = t4[0]; bf[np * 2][1] = t4[1];
                bf[np * 2 + 1][0] = t4[2]; bf[np * 2 + 1][1] = t4[3];
            }
#pragma unroll
            for (int mt = 0; mt < 2; mt++)
#pragma unroll
                for (int nt = 0; nt < 8; nt++)
                    mmah(acc[mt][nt], af[mt], bf[nt]);
        }
        __syncthreads();
        buf ^= 1;
    }

    // epilogue: ctx = fp16(acc * inv), layout [B,S,D]
#pragma unroll
    for (int mt = 0; mt < 2; mt++) {
#pragma unroll
        for (int hf = 0; hf < 2; hf++) {
            int lrow = wid * 32 + mt * 16 + gid + hf * 8;
            int qrow = q0 + lrow;
            float invE = sinv[lrow];
            __half* crow = ctx + ((size_t)b * SEQ + qrow) * DMODEL + h * HDIM;
#pragma unroll
            for (int nt = 0; nt < 8; nt++) {
                int d = nt * 8 + t2;
                *(__half2*)(crow + d) = __floats2half2_rn(acc[mt][nt][hf * 2 + 0] * invE,
                                                          acc[mt][nt][hf * 2 + 1] * invE);
            }
        }
    }
}

// -------------------- launcher ----------------------------------------------
extern "C" void kernel_launch(void* const* d_in, const int* in_sizes, int n_in,
                              void* d_out, int out_size)
{
    const float* x  = (const float*)d_in[0];
    const float* Wq = (const float*)d_in[1];
    const float* bq = (const float*)d_in[2];
    const float* Wk = (const float*)d_in[3];
    const float* bk = (const float*)d_in[4];
    const float* Wv = (const float*)d_in[5];
    const float* bv = (const float*)d_in[6];
    const float* Wo = (const float*)d_in[7];
    const float* bo = (const float*)d_in[8];

    float* out_ptr  = (float*)d_out;                                   // [B,S,D]
    float* attn_ptr = (float*)d_out + (size_t)BATCH * SEQ * DMODEL;    // [B,H,S,S]

    __half *qp, *kp, *vtp, *cp, *xh, *wh, *ep;
    float *rs;
    cudaGetSymbolAddress((void**)&qp, g_qh);
    cudaGetSymbolAddress((void**)&kp, g_kh);
    cudaGetSymbolAddress((void**)&vtp, g_vt);
    cudaGetSymbolAddress((void**)&cp, g_ch);
    cudaGetSymbolAddress((void**)&rs, g_rowsum);
    cudaGetSymbolAddress((void**)&xh, g_xh);
    cudaGetSymbolAddress((void**)&wh, g_wh);
    cudaGetSymbolAddress((void**)&ep, g_eh);

    cudaFuncSetAttribute(qkv_h_kernel,
                         cudaFuncAttributeMaxDynamicSharedMemorySize, PROJ_SMEM_BYTES);
    cudaFuncSetAttribute(proj_o_kernel,
                         cudaFuncAttributeMaxDynamicSharedMemorySize, PROJ_SMEM_BYTES);
    cudaFuncSetAttribute(scores_h_kernel,
                         cudaFuncAttributeMaxDynamicSharedMemorySize, SCORES_SMEM_BYTES);
    cudaFuncSetAttribute(ctx_h_kernel,
                         cudaFuncAttributeMaxDynamicSharedMemorySize, CTX_SMEM_BYTES);

    dim3 blk(256);

    // merged fp32 -> fp16 conversion (x + 4 weights in one launch)
    const size_t WSZ = (size_t)DMODEL * DMODEL;
    int total8 = (int)(XN8 + 4 * WN8);          // 1572864
    tohalf_all_kernel<<<total8 / 256, blk>>>(x, Wq, Wk, Wv, Wo, xh, wh);

    // fused Q/K/V projection: grid.z = 3
    dim3 qkvgrid(DMODEL / 128, MTOT / 128, 3);  // (8, 64, 3)
    qkv_h_kernel<<<qkvgrid, blk, PROJ_SMEM_BYTES>>>(
        xh, wh + 0 * WSZ, wh + 1 * WSZ, wh + 2 * WSZ, bq, bk, bv, qp, kp, vtp);

    dim3 sgrid(SEQ / 128, SEQ / 128, BATCH * HEADS);   // (8, 8, 128)
    scores_h_kernel<<<sgrid, blk, SCORES_SMEM_BYTES>>>(qp, kp, ep, rs);

    dim3 cgrid(SEQ / 256, BATCH * HEADS);              // (4, 128)
    ctx_h_kernel<<<cgrid, blk, CTX_SMEM_BYTES>>>(ep, vtp, rs, attn_ptr, cp);

    dim3 ogrid(DMODEL / 128, MTOT / 128);              // (8, 64)
    proj_o_kernel<<<ogrid, blk, PROJ_SMEM_BYTES>>>(cp, wh + 3 * WSZ, bo, out_ptr);
}